// round 3
// baseline (speedup 1.0000x reference)
#include <cuda_runtime.h>
#include <math.h>

// Problem constants
#define BB 2
#define SS 512
#define EE 256
#define HH 8
#define DD 32
#define MM (BB*SS)          // 1024 tokens
#define MAXN 0.99999f       // (1 - 1e-5) / sqrt(C), C = 1
#define EPS15 1e-15f
#define DELTA7 1e-7f

// ---------------- scratch (device globals; no runtime allocation) ----------------
__device__ float g_mx [MM * 3 * EE];     // qkv GEMM result (1024 x 768)
__device__ float g_q  [MM * EE];
__device__ float g_k  [MM * EE];
__device__ float g_lv [MM * EE];         // logmap0(v), per head
__device__ float g_qn [BB*HH*SS];
__device__ float g_iqn[BB*HH*SS];
__device__ float g_kn [BB*HH*SS];
__device__ float g_ikn[BB*HH*SS];
__device__ float g_w  [BB*HH*SS*SS];     // unnormalized weights, 16 MB (L2-resident)
__device__ float g_ao [MM * EE];         // attention output (after expmap0)
__device__ float g_mx2[MM * EE];         // out-proj GEMM result

// ---------------- reductions ----------------
__device__ __forceinline__ float warp_red(float v) {
#pragma unroll
    for (int o = 16; o; o >>= 1) v += __shfl_xor_sync(0xffffffffu, v, o);
    return v;
}

// block of 256 threads; sbuf must hold >= 9 floats
__device__ __forceinline__ float block_red(float v, float* sbuf) {
    int lane = threadIdx.x & 31, wid = threadIdx.x >> 5;
    v = warp_red(v);
    if (lane == 0) sbuf[wid] = v;
    __syncthreads();
    if (wid == 0) {
        float x = (lane < 8) ? sbuf[lane] : 0.f;
        x = warp_red(x);
        if (lane == 0) sbuf[8] = x;
    }
    __syncthreads();
    return sbuf[8];
}

// ---------------- GEMM: out[r][c] = sum_k A[r][k] * W[c][k] ----------------
// A: (1024, 256) row-major. W selected per 64-col tile (cols 0-255 -> W0, 256-511 -> W1, 512-767 -> W2).
__global__ __launch_bounds__(256) void gemm64(
    const float* __restrict__ A,
    const float* __restrict__ W0, const float* __restrict__ W1, const float* __restrict__ W2,
    float* __restrict__ out, int ldo)
{
    __shared__ __align__(16) float aT[32][68];
    __shared__ __align__(16) float wT[32][68];
    int r0  = blockIdx.x * 64;
    int cg0 = blockIdx.y * 64;
    int wsel = cg0 >> 8;
    const float* W = (wsel == 0) ? W0 : ((wsel == 1) ? W1 : W2);
    int wc0 = cg0 & 255;
    int t = threadIdx.x;
    int ty = t >> 4, tx = t & 15;
    float acc[4][4] = {};

    for (int kt = 0; kt < 8; kt++) {
        int kb = kt * 32;
#pragma unroll
        for (int it = 0; it < 8; it++) {
            int e = t + it * 256;
            int r = e >> 5, j = e & 31;
            aT[j][r] = A[(r0 + r) * 256 + kb + j];
            wT[j][r] = W[(wc0 + r) * 256 + kb + j];
        }
        __syncthreads();
#pragma unroll
        for (int j = 0; j < 32; j++) {
            float4 a = *(const float4*)&aT[j][ty * 4];
            float4 b = *(const float4*)&wT[j][tx * 4];
            float av[4] = {a.x, a.y, a.z, a.w};
            float bv[4] = {b.x, b.y, b.z, b.w};
#pragma unroll
            for (int i = 0; i < 4; i++)
#pragma unroll
                for (int jj = 0; jj < 4; jj++)
                    acc[i][jj] = fmaf(av[i], bv[jj], acc[i][jj]);
        }
        __syncthreads();
    }
#pragma unroll
    for (int i = 0; i < 4; i++) {
        float4 v = make_float4(acc[i][0], acc[i][1], acc[i][2], acc[i][3]);
        *(float4*)&out[(r0 + ty * 4 + i) * ldo + cg0 + tx * 4] = v;
    }
}

// ---------------- per-token QKV postprocess ----------------
// hyp_linear tail: mobius_matvec scaling + mobius_add(b); then clamp q/k,
// per-head norms (warp == head since D == 32), logmap0(v).
__global__ __launch_bounds__(256) void post_qkv(
    const float* __restrict__ x,
    const float* __restrict__ bq, const float* __restrict__ bk, const float* __restrict__ bv)
{
    __shared__ float sbuf[9];
    int token = blockIdx.x;
    int t = threadIdx.x;
    int lane = t & 31, wid = t >> 5;

    float xe = x[token * EE + t];
    float xn2 = block_red(xe * xe, sbuf);
    float xn = sqrtf(fmaxf(xn2, EPS15));
    float at = atanhf(fminf(xn, 1.f - 1e-5f));   // SC = 1

    int b = token >> 9, s = token & 511;
    int hidx = (b * HH + wid) * SS + s;

#pragma unroll
    for (int w = 0; w < 3; w++) {
        const float* bvec = (w == 0) ? bq : ((w == 1) ? bk : bv);
        float m  = g_mx[token * (3 * EE) + w * EE + t];
        float be = bvec[t];
        float sm2 = block_red(m * m, sbuf);
        float mxn = sqrtf(fmaxf(sm2, EPS15));
        float factor = tanhf(mxn / xn * at) / mxn;   // / (mxn * SC)
        float mm = factor * m;
        float x2 = factor * factor * sm2;
        float xy = block_red(mm * be, sbuf);
        float y2 = block_red(be * be, sbuf);
        float u  = 1.f + 2.f * xy + y2;              // C = 1
        float num = u * mm + (1.f - x2) * be;
        float den = 1.f + 2.f * xy + x2 * y2;
        float res = num / (den + EPS15);

        if (w < 2) {
            res = fminf(res, MAXN);
            float hn = warp_red(res * res);          // per-head norm^2 (all lanes)
            if (w == 0) {
                g_q[token * EE + t] = res;
                if (lane == 0) { g_qn[hidx] = hn; g_iqn[hidx] = 1.f / (1.f - hn); }
            } else {
                g_k[token * EE + t] = res;
                if (lane == 0) { g_kn[hidx] = hn; g_ikn[hidx] = 1.f / (1.f - hn); }
            }
        } else {
            float vn2 = warp_red(res * res);
            float vn = sqrtf(fmaxf(vn2, EPS15));
            float lf = atanhf(fminf(vn, 1.f - 1e-5f)) / vn;
            g_lv[token * EE + t] = lf * res;
        }
    }
}

// ---------------- scores: QK^T + closed-form hyperbolic-distance -> weight ----------------
__global__ __launch_bounds__(256) void scores_k(const float* __restrict__ hs)
{
    __shared__ __align__(16) float qT[32][68];
    __shared__ __align__(16) float kT[32][68];
    __shared__ float qns[64], iqs[64], kns[64], iks[64];

    int qt = blockIdx.x, kt = blockIdx.y, bh = blockIdx.z;
    int b = bh >> 3, h = bh & 7;
    int q0 = qt * 64, k0 = kt * 64;
    int t = threadIdx.x;

#pragma unroll
    for (int it = 0; it < 8; it++) {
        int e = t + it * 256;
        int r = e >> 5, j = e & 31;
        qT[j][r] = g_q[(b * SS + q0 + r) * EE + h * DD + j];
        kT[j][r] = g_k[(b * SS + k0 + r) * EE + h * DD + j];
    }
    {
        int g = t >> 6, i = t & 63;
        int qi = bh * SS + q0 + i;
        int ki = bh * SS + k0 + i;
        if (g == 0)      qns[i] = g_qn[qi];
        else if (g == 1) iqs[i] = g_iqn[qi];
        else if (g == 2) kns[i] = g_kn[ki];
        else             iks[i] = g_ikn[ki];
    }
    __syncthreads();

    int ty = t >> 4, tx = t & 15;
    float acc[4][4] = {};
#pragma unroll
    for (int j = 0; j < 32; j++) {
        float4 a = *(const float4*)&qT[j][ty * 4];
        float4 bb = *(const float4*)&kT[j][tx * 4];
        float av[4] = {a.x, a.y, a.z, a.w};
        float bv[4] = {bb.x, bb.y, bb.z, bb.w};
#pragma unroll
        for (int i = 0; i < 4; i++)
#pragma unroll
            for (int jj = 0; jj < 4; jj++)
                acc[i][jj] = fmaf(av[i], bv[jj], acc[i][jj]);
    }

    float cc = 1.f / (hs[h] * 5.656854249f);   // 1/(head_scaling * sqrt(D)), D = 32

#pragma unroll
    for (int i = 0; i < 4; i++) {
        float q2 = qns[ty * 4 + i], iq = iqs[ty * 4 + i];
        float wout[4];
#pragma unroll
        for (int j = 0; j < 4; j++) {
            float k2 = kns[tx * 4 + j], ik = iks[tx * 4 + j];
            float xy = -acc[i][j];
            float u  = 1.f + 2.f * xy + q2;
            float vf = 1.f - k2;
            float num2 = u * u * k2 + vf * vf * q2 + 2.f * u * vf * xy;
            float den  = 1.f + 2.f * xy + k2 * q2;
            float rd = __fdividef(1.f, den);
            float dn = num2 * rd * rd;
            float am1 = fmaxf(2.f * dn * iq * ik, DELTA7);
            float z = (1.f + am1) + sqrtf(am1 * (2.f + am1));   // a + sqrt(a^2-1)
            wout[j] = __expf(-cc * __logf(z));
        }
        float4 v = make_float4(wout[0], wout[1], wout[2], wout[3]);
        *(float4*)&g_w[(bh * SS + q0 + ty * 4 + i) * SS + k0 + tx * 4] = v;
    }
}

// ---------------- AV: out = softmax(w) @ lv, then expmap0 per head ----------------
__global__ __launch_bounds__(256) void av_k()
{
    __shared__ __align__(16) float wT[64][68];   // [key][query-row]
    __shared__ __align__(16) float lvs[64][32];  // [key][d]
    __shared__ float os[64][33];

    int qt = blockIdx.x, bh = blockIdx.y;
    int b = bh >> 3, h = bh & 7;
    int q0 = qt * 64;
    int t = threadIdx.x;
    int ty = t >> 4, tx = t & 15;

    float acc[4][2] = {};
    float rs[4] = {};

    for (int c0 = 0; c0 < SS; c0 += 64) {
#pragma unroll
        for (int it = 0; it < 16; it++) {
            int e = t + it * 256;
            int r = e >> 6, c = e & 63;
            wT[c][r] = g_w[(bh * SS + q0 + r) * SS + c0 + c];
        }
#pragma unroll
        for (int it = 0; it < 8; it++) {
            int e = t + it * 256;
            int r = e >> 5, d = e & 31;
            lvs[r][d] = g_lv[(b * SS + c0 + r) * EE + h * DD + d];
        }
        __syncthreads();
#pragma unroll
        for (int c = 0; c < 64; c++) {
            float4 a = *(const float4*)&wT[c][ty * 4];
            float2 lv2 = *(const float2*)&lvs[c][tx * 2];
            float av[4] = {a.x, a.y, a.z, a.w};
#pragma unroll
            for (int i = 0; i < 4; i++) {
                acc[i][0] = fmaf(av[i], lv2.x, acc[i][0]);
                acc[i][1] = fmaf(av[i], lv2.y, acc[i][1]);
                rs[i] += av[i];
            }
        }
        __syncthreads();
    }

#pragma unroll
    for (int i = 0; i < 4; i++) {
        float ir = __fdividef(1.f, rs[i]);
        os[ty * 4 + i][tx * 2]     = acc[i][0] * ir;
        os[ty * 4 + i][tx * 2 + 1] = acc[i][1] * ir;
    }
    __syncthreads();

    int wid = t >> 5, lane = t & 31;
#pragma unroll
    for (int rr = 0; rr < 8; rr++) {
        int row = wid * 8 + rr;
        float v = os[row][lane];
        float n2 = warp_red(v * v);
        float un = sqrtf(fmaxf(n2, EPS15));
        float f = tanhf(un) / un;   // SC = 1
        g_ao[(b * SS + q0 + row) * EE + h * DD + lane] = f * v;
    }
}

// ---------------- final hyp_linear tail -> d_out ----------------
__global__ __launch_bounds__(256) void post_out(const float* __restrict__ bo, float* __restrict__ out)
{
    __shared__ float sbuf[9];
    int token = blockIdx.x;
    int t = threadIdx.x;

    float xe = g_ao[token * EE + t];
    float xn2 = block_red(xe * xe, sbuf);
    float xn = sqrtf(fmaxf(xn2, EPS15));
    float at = atanhf(fminf(xn, 1.f - 1e-5f));

    float m  = g_mx2[token * EE + t];
    float be = bo[t];
    float sm2 = block_red(m * m, sbuf);
    float mxn = sqrtf(fmaxf(sm2, EPS15));
    float factor = tanhf(mxn / xn * at) / mxn;
    float mm = factor * m;
    float x2 = factor * factor * sm2;
    float xy = block_red(mm * be, sbuf);
    float y2 = block_red(be * be, sbuf);
    float u  = 1.f + 2.f * xy + y2;
    float num = u * mm + (1.f - x2) * be;
    float den = 1.f + 2.f * xy + x2 * y2;
    out[token * EE + t] = num / (den + EPS15);
}

// ---------------- launch ----------------
extern "C" void kernel_launch(void* const* d_in, const int* in_sizes, int n_in,
                              void* d_out, int out_size)
{
    const float* x  = (const float*)d_in[0];
    const float* Wq = (const float*)d_in[1];
    const float* bq = (const float*)d_in[2];
    const float* Wk = (const float*)d_in[3];
    const float* bk = (const float*)d_in[4];
    const float* Wv = (const float*)d_in[5];
    const float* bv = (const float*)d_in[6];
    const float* Wo = (const float*)d_in[7];
    const float* bo = (const float*)d_in[8];
    const float* hs = (const float*)d_in[9];
    float* out = (float*)d_out;

    float *mx, *mx2, *ao;
    cudaGetSymbolAddress((void**)&mx,  g_mx);
    cudaGetSymbolAddress((void**)&mx2, g_mx2);
    cudaGetSymbolAddress((void**)&ao,  g_ao);

    gemm64  <<<dim3(16, 12), 256>>>(x, Wq, Wk, Wv, mx, 3 * EE);
    post_qkv<<<MM, 256>>>(x, bq, bk, bv);
    scores_k<<<dim3(8, 8, BB * HH), 256>>>(hs);
    av_k    <<<dim3(8, BB * HH), 256>>>();
    gemm64  <<<dim3(16, 4), 256>>>(ao, Wo, Wo, Wo, mx2, EE);
    post_out<<<MM, 256>>>(bo, out);
}

// round 4
// speedup vs baseline: 1.0741x; 1.0741x over previous
#include <cuda_runtime.h>
#include <math.h>

// Problem constants
#define BB 2
#define SS 512
#define EE 256
#define HH 8
#define DD 32
#define MM (BB*SS)          // 1024 tokens
#define MAXN 0.99999f       // (1 - 1e-5) / sqrt(C), C = 1
#define EPS15 1e-15f
#define DELTA7 1e-7f

// ---------------- scratch (device globals; no runtime allocation) ----------------
__device__ float g_mx [MM * 3 * EE];     // qkv GEMM result (1024 x 768)
__device__ float g_q  [MM * EE];
__device__ float g_k  [MM * EE];
__device__ float g_lv [MM * EE];         // logmap0(v), per head
__device__ float g_qn [BB*HH*SS];
__device__ float g_iqn[BB*HH*SS];
__device__ float g_kn [BB*HH*SS];
__device__ float g_ikn[BB*HH*SS];
__device__ float g_ao [MM * EE];         // attention output (after expmap0)
__device__ float g_mx2[MM * EE];         // out-proj GEMM result

// ---------------- reductions ----------------
__device__ __forceinline__ float warp_red(float v) {
#pragma unroll
    for (int o = 16; o; o >>= 1) v += __shfl_xor_sync(0xffffffffu, v, o);
    return v;
}
// sum over 4-lane group (one head: lane holds 8 of the head's 32 elems)
__device__ __forceinline__ float grp4_red(float v) {
    v += __shfl_xor_sync(0xffffffffu, v, 1);
    v += __shfl_xor_sync(0xffffffffu, v, 2);
    return v;
}
__device__ __forceinline__ float dot4(float4 a, float4 b) {
    return a.x*b.x + a.y*b.y + a.z*b.z + a.w*b.w;
}

// ---------------- GEMM: out[r][c] = sum_k A[r][k] * W[c][k] ----------------
__global__ __launch_bounds__(256) void gemm64(
    const float* __restrict__ A,
    const float* __restrict__ W0, const float* __restrict__ W1, const float* __restrict__ W2,
    float* __restrict__ out, int ldo)
{
    __shared__ __align__(16) float aT[32][68];
    __shared__ __align__(16) float wT[32][68];
    int r0  = blockIdx.x * 64;
    int cg0 = blockIdx.y * 64;
    int wsel = cg0 >> 8;
    const float* W = (wsel == 0) ? W0 : ((wsel == 1) ? W1 : W2);
    int wc0 = cg0 & 255;
    int t = threadIdx.x;
    int ty = t >> 4, tx = t & 15;
    float acc[4][4] = {};

    for (int kt = 0; kt < 8; kt++) {
        int kb = kt * 32;
#pragma unroll
        for (int it = 0; it < 8; it++) {
            int e = t + it * 256;
            int r = e >> 5, j = e & 31;
            aT[j][r] = A[(r0 + r) * 256 + kb + j];
            wT[j][r] = W[(wc0 + r) * 256 + kb + j];
        }
        __syncthreads();
#pragma unroll
        for (int j = 0; j < 32; j++) {
            float4 a = *(const float4*)&aT[j][ty * 4];
            float4 b = *(const float4*)&wT[j][tx * 4];
            float av[4] = {a.x, a.y, a.z, a.w};
            float bv[4] = {b.x, b.y, b.z, b.w};
#pragma unroll
            for (int i = 0; i < 4; i++)
#pragma unroll
                for (int jj = 0; jj < 4; jj++)
                    acc[i][jj] = fmaf(av[i], bv[jj], acc[i][jj]);
        }
        __syncthreads();
    }
#pragma unroll
    for (int i = 0; i < 4; i++) {
        float4 v = make_float4(acc[i][0], acc[i][1], acc[i][2], acc[i][3]);
        *(float4*)&out[(r0 + ty * 4 + i) * ldo + cg0 + tx * 4] = v;
    }
}

// ---------------- per-token QKV postprocess: warp-per-token, shfl-only ----------------
__global__ __launch_bounds__(256) void post_qkv_w(
    const float* __restrict__ x,
    const float* __restrict__ bq, const float* __restrict__ bk, const float* __restrict__ bv)
{
    int wid = threadIdx.x >> 5, lane = threadIdx.x & 31;
    int token = blockIdx.x * 8 + wid;

    const float4* xr = (const float4*)(x + token * EE);
    float4 xa = xr[lane * 2], xb = xr[lane * 2 + 1];
    float xn2 = warp_red(dot4(xa, xa) + dot4(xb, xb));
    float xn = sqrtf(fmaxf(xn2, EPS15));
    float at = atanhf(fminf(xn, 1.f - 1e-5f));   // SC = 1

    int b = token >> 9, s = token & 511;
    int h = lane >> 2;
    int hidx = (b * HH + h) * SS + s;

#pragma unroll
    for (int w = 0; w < 3; w++) {
        const float* bvec = (w == 0) ? bq : ((w == 1) ? bk : bv);
        const float4* mr = (const float4*)(g_mx + token * (3 * EE) + w * EE);
        float4 ma = mr[lane * 2], mb = mr[lane * 2 + 1];
        const float4* br = (const float4*)bvec;
        float4 ba = br[lane * 2], bb4 = br[lane * 2 + 1];

        float sm2 = warp_red(dot4(ma, ma) + dot4(mb, mb));
        float mxn = sqrtf(fmaxf(sm2, EPS15));
        float factor = tanhf(mxn / xn * at) / mxn;
        float x2 = factor * factor * sm2;
        float xy = warp_red(factor * (dot4(ma, ba) + dot4(mb, bb4)));
        float y2 = warp_red(dot4(ba, ba) + dot4(bb4, bb4));
        float u  = 1.f + 2.f * xy + y2;
        float idn = 1.f / (1.f + 2.f * xy + x2 * y2 + EPS15);
        float c1 = u * factor;       // res = (c1*m + c2*b) * idn
        float c2 = 1.f - x2;

        float r0 = (c1 * ma.x + c2 * ba.x) * idn;
        float r1 = (c1 * ma.y + c2 * ba.y) * idn;
        float r2 = (c1 * ma.z + c2 * ba.z) * idn;
        float r3 = (c1 * ma.w + c2 * ba.w) * idn;
        float r4 = (c1 * mb.x + c2 * bb4.x) * idn;
        float r5 = (c1 * mb.y + c2 * bb4.y) * idn;
        float r6 = (c1 * mb.z + c2 * bb4.z) * idn;
        float r7 = (c1 * mb.w + c2 * bb4.w) * idn;

        if (w < 2) {
            r0 = fminf(r0, MAXN); r1 = fminf(r1, MAXN); r2 = fminf(r2, MAXN); r3 = fminf(r3, MAXN);
            r4 = fminf(r4, MAXN); r5 = fminf(r5, MAXN); r6 = fminf(r6, MAXN); r7 = fminf(r7, MAXN);
            float hn = grp4_red(r0*r0 + r1*r1 + r2*r2 + r3*r3 + r4*r4 + r5*r5 + r6*r6 + r7*r7);
            float4* dst = (float4*)((w == 0 ? g_q : g_k) + token * EE);
            dst[lane * 2]     = make_float4(r0, r1, r2, r3);
            dst[lane * 2 + 1] = make_float4(r4, r5, r6, r7);
            if ((lane & 3) == 0) {
                if (w == 0) { g_qn[hidx] = hn; g_iqn[hidx] = 1.f / (1.f - hn); }
                else        { g_kn[hidx] = hn; g_ikn[hidx] = 1.f / (1.f - hn); }
            }
        } else {
            float vn2 = grp4_red(r0*r0 + r1*r1 + r2*r2 + r3*r3 + r4*r4 + r5*r5 + r6*r6 + r7*r7);
            float vn = sqrtf(fmaxf(vn2, EPS15));
            float lf = atanhf(fminf(vn, 1.f - 1e-5f)) / vn;
            float4* dst = (float4*)(g_lv + token * EE);
            dst[lane * 2]     = make_float4(lf*r0, lf*r1, lf*r2, lf*r3);
            dst[lane * 2 + 1] = make_float4(lf*r4, lf*r5, lf*r6, lf*r7);
        }
    }
}

// ---------------- fused attention: scores + transform + AV, weights stay in smem ----------------
__global__ __launch_bounds__(256) void attn_fused(const float* __restrict__ hs)
{
    __shared__ __align__(16) float qT[32 * 68];   // [d][qrow]; reused as osS (64 x 34) at tail
    __shared__ __align__(16) float kT[32 * 68];   // [d][krow]; reused as rsS (64 x 17) at tail
    __shared__ __align__(16) float wS[64 * 68];   // weights [qrow][kcol]
    __shared__ __align__(16) float lvS[64 * 36];  // lv [krow][d]
    __shared__ float qns[64], iqs[64], kns[64], iks[64];   // qns reused as rsF at tail

    int qt = blockIdx.x, bh = blockIdx.y;
    int b = bh >> 3, h = bh & 7;
    int q0 = qt * 64;
    int t = threadIdx.x;
    int ty = t >> 4, tx = t & 15;     // scores mapping: q rows ty*4+i, k cols tx*4+j
    int ty2 = t >> 3, tx2 = t & 7;    // AV mapping: q rows ty2*2+{0,1}, d cols tx2*4..+3

    // load Q tile once
#pragma unroll
    for (int it = 0; it < 8; it++) {
        int e = t + it * 256;
        int r = e >> 5, j = e & 31;
        qT[j * 68 + r] = g_q[(b * SS + q0 + r) * EE + h * DD + j];
    }
    if (t < 64) { qns[t] = g_qn[bh * SS + q0 + t]; iqs[t] = g_iqn[bh * SS + q0 + t]; }

    float negcc = -1.f / (hs[h] * 5.656854249f);   // -1/(head_scaling*sqrt(32))
    float av0[4] = {}, av1[4] = {};
    float rs[4] = {};

    for (int c0 = 0; c0 < SS; c0 += 64) {
        // load K chunk + lv chunk + key norms
#pragma unroll
        for (int it = 0; it < 8; it++) {
            int e = t + it * 256;
            int r = e >> 5, j = e & 31;
            kT[j * 68 + r]  = g_k [(b * SS + c0 + r) * EE + h * DD + j];
            lvS[r * 36 + j] = g_lv[(b * SS + c0 + r) * EE + h * DD + j];
        }
        if (t < 64) { kns[t] = g_kn[bh * SS + c0 + t]; iks[t] = g_ikn[bh * SS + c0 + t]; }
        __syncthreads();   // A: tiles ready (also guards first-iter qT, and prev-iter AV done)

        // scores GEMM: acc[i][j] = q . k
        float acc[4][4] = {};
#pragma unroll
        for (int j = 0; j < 32; j++) {
            float4 a  = *(const float4*)&qT[j * 68 + ty * 4];
            float4 bb = *(const float4*)&kT[j * 68 + tx * 4];
            float avr[4] = {a.x, a.y, a.z, a.w};
            float bvr[4] = {bb.x, bb.y, bb.z, bb.w};
#pragma unroll
            for (int i = 0; i < 4; i++)
#pragma unroll
                for (int jj = 0; jj < 4; jj++)
                    acc[i][jj] = fmaf(avr[i], bvr[jj], acc[i][jj]);
        }

        // transform scores -> unnormalized weights (+ row-sum partials)
        float k2v[4], ikv[4], vfv[4], vf2v[4];
#pragma unroll
        for (int j = 0; j < 4; j++) {
            k2v[j] = kns[tx * 4 + j];
            ikv[j] = iks[tx * 4 + j];
            vfv[j] = 1.f - k2v[j];
            vf2v[j] = vfv[j] * vfv[j];
        }
#pragma unroll
        for (int i = 0; i < 4; i++) {
            float q2  = qns[ty * 4 + i];
            float iq2 = 2.f * iqs[ty * 4 + i];
#pragma unroll
            for (int j = 0; j < 4; j++) {
                float xy  = -acc[i][j];
                float t0  = fmaf(2.f, xy, 1.f);
                float u   = t0 + q2;
                float den = fmaf(k2v[j], q2, t0);
                float rd  = __fdividef(1.f, den);
                float num2 = fmaf(u * u, k2v[j], vf2v[j] * q2);
                num2 = fmaf(u * vfv[j], xy + xy, num2);
                float dn  = num2 * rd * rd;
                float am1 = fmaxf(dn * (iq2 * ikv[j]), DELTA7);
                float z   = (1.f + am1) + sqrtf(fmaf(am1, am1, am1 + am1));
                float wv  = exp2f(negcc * __log2f(z));
                rs[i] += wv;
                acc[i][j] = wv;
            }
        }
        // stage weights to smem [q][c]
#pragma unroll
        for (int i = 0; i < 4; i++)
            *(float4*)&wS[(ty * 4 + i) * 68 + tx * 4] =
                make_float4(acc[i][0], acc[i][1], acc[i][2], acc[i][3]);
        __syncthreads();   // B: weights visible

        // AV accumulate: out[q][d] += w[q][c] * lv[c][d]
        const float* wp0 = &wS[(ty2 * 2) * 68];
        const float* wp1 = wp0 + 68;
        const float* lp  = &lvS[tx2 * 4];
#pragma unroll 8
        for (int c = 0; c < 64; c += 2) {
            float2 wa = *(const float2*)(wp0 + c);
            float2 wb = *(const float2*)(wp1 + c);
            float4 l0 = *(const float4*)(lp + c * 36);
            float4 l1 = *(const float4*)(lp + (c + 1) * 36);
            av0[0] = fmaf(wa.x, l0.x, av0[0]); av0[0] = fmaf(wa.y, l1.x, av0[0]);
            av0[1] = fmaf(wa.x, l0.y, av0[1]); av0[1] = fmaf(wa.y, l1.y, av0[1]);
            av0[2] = fmaf(wa.x, l0.z, av0[2]); av0[2] = fmaf(wa.y, l1.z, av0[2]);
            av0[3] = fmaf(wa.x, l0.w, av0[3]); av0[3] = fmaf(wa.y, l1.w, av0[3]);
            av1[0] = fmaf(wb.x, l0.x, av1[0]); av1[0] = fmaf(wb.y, l1.x, av1[0]);
            av1[1] = fmaf(wb.x, l0.y, av1[1]); av1[1] = fmaf(wb.y, l1.y, av1[1]);
            av1[2] = fmaf(wb.x, l0.z, av1[2]); av1[2] = fmaf(wb.y, l1.z, av1[2]);
            av1[3] = fmaf(wb.x, l0.w, av1[3]); av1[3] = fmaf(wb.y, l1.w, av1[3]);
        }
        __syncthreads();   // C: AV done before next chunk overwrites kT/lvS/wS
    }

    // row-sum reduction across the 16 tx lanes (reuse kT as 64x17 buffer)
    float* rsS = kT;
#pragma unroll
    for (int i = 0; i < 4; i++) rsS[(ty * 4 + i) * 17 + tx] = rs[i];
    __syncthreads();
    float* rsF = qns;   // reuse
    if (t < 64) {
        float s = 0.f;
#pragma unroll
        for (int xx = 0; xx < 16; xx++) s += rsS[t * 17 + xx];
        rsF[t] = __fdividef(1.f, s);
    }
    __syncthreads();

    // normalize + stage to osS (reuse qT as 64x34)
    float* osS = qT;
    {
        int qa = ty2 * 2;
        float ir0 = rsF[qa], ir1 = rsF[qa + 1];
        *(float2*)&osS[qa * 34 + tx2 * 4]           = make_float2(av0[0] * ir0, av0[1] * ir0);
        *(float2*)&osS[qa * 34 + tx2 * 4 + 2]       = make_float2(av0[2] * ir0, av0[3] * ir0);
        *(float2*)&osS[(qa + 1) * 34 + tx2 * 4]     = make_float2(av1[0] * ir1, av1[1] * ir1);
        *(float2*)&osS[(qa + 1) * 34 + tx2 * 4 + 2] = make_float2(av1[2] * ir1, av1[3] * ir1);
    }
    __syncthreads();

    // expmap0 per head row (warp over d = 32)
    int wid = t >> 5, lane = t & 31;
#pragma unroll
    for (int rr = 0; rr < 8; rr++) {
        int row = wid * 8 + rr;
        float v = osS[row * 34 + lane];
        float n2 = warp_red(v * v);
        float un = sqrtf(fmaxf(n2, EPS15));
        float f = tanhf(un) / un;   // SC = 1
        g_ao[(b * SS + q0 + row) * EE + h * DD + lane] = f * v;
    }
}

// ---------------- final hyp_linear tail: warp-per-token ----------------
__global__ __launch_bounds__(256) void post_out_w(const float* __restrict__ bo, float* __restrict__ out)
{
    int wid = threadIdx.x >> 5, lane = threadIdx.x & 31;
    int token = blockIdx.x * 8 + wid;

    const float4* xr = (const float4*)(g_ao + token * EE);
    float4 xa = xr[lane * 2], xb = xr[lane * 2 + 1];
    float xn2 = warp_red(dot4(xa, xa) + dot4(xb, xb));
    float xn = sqrtf(fmaxf(xn2, EPS15));
    float at = atanhf(fminf(xn, 1.f - 1e-5f));

    const float4* mr = (const float4*)(g_mx2 + token * EE);
    float4 ma = mr[lane * 2], mb = mr[lane * 2 + 1];
    const float4* br = (const float4*)bo;
    float4 ba = br[lane * 2], bb4 = br[lane * 2 + 1];

    float sm2 = warp_red(dot4(ma, ma) + dot4(mb, mb));
    float mxn = sqrtf(fmaxf(sm2, EPS15));
    float factor = tanhf(mxn / xn * at) / mxn;
    float x2 = factor * factor * sm2;
    float xy = warp_red(factor * (dot4(ma, ba) + dot4(mb, bb4)));
    float y2 = warp_red(dot4(ba, ba) + dot4(bb4, bb4));
    float u  = 1.f + 2.f * xy + y2;
    float idn = 1.f / (1.f + 2.f * xy + x2 * y2 + EPS15);
    float c1 = u * factor;
    float c2 = 1.f - x2;

    float4* dst = (float4*)(out + token * EE);
    dst[lane * 2] = make_float4(
        (c1 * ma.x + c2 * ba.x) * idn, (c1 * ma.y + c2 * ba.y) * idn,
        (c1 * ma.z + c2 * ba.z) * idn, (c1 * ma.w + c2 * ba.w) * idn);
    dst[lane * 2 + 1] = make_float4(
        (c1 * mb.x + c2 * bb4.x) * idn, (c1 * mb.y + c2 * bb4.y) * idn,
        (c1 * mb.z + c2 * bb4.z) * idn, (c1 * mb.w + c2 * bb4.w) * idn);
}

// ---------------- launch ----------------
extern "C" void kernel_launch(void* const* d_in, const int* in_sizes, int n_in,
                              void* d_out, int out_size)
{
    const float* x  = (const float*)d_in[0];
    const float* Wq = (const float*)d_in[1];
    const float* bq = (const float*)d_in[2];
    const float* Wk = (const float*)d_in[3];
    const float* bk = (const float*)d_in[4];
    const float* Wv = (const float*)d_in[5];
    const float* bv = (const float*)d_in[6];
    const float* Wo = (const float*)d_in[7];
    const float* bo = (const float*)d_in[8];
    const float* hs = (const float*)d_in[9];
    float* out = (float*)d_out;

    float *mx, *mx2, *ao;
    cudaGetSymbolAddress((void**)&mx,  g_mx);
    cudaGetSymbolAddress((void**)&mx2, g_mx2);
    cudaGetSymbolAddress((void**)&ao,  g_ao);

    gemm64     <<<dim3(16, 12), 256>>>(x, Wq, Wk, Wv, mx, 3 * EE);
    post_qkv_w <<<MM / 8, 256>>>(x, bq, bk, bv);
    attn_fused <<<dim3(8, BB * HH), 256>>>(hs);
    gemm64     <<<dim3(16, 4), 256>>>(ao, Wo, Wo, Wo, mx2, EE);
    post_out_w <<<MM / 8, 256>>>(bo, out);
}

// round 5
// speedup vs baseline: 1.2954x; 1.2060x over previous
#include <cuda_runtime.h>
#include <math.h>

// Problem constants
#define BB 2
#define SS 512
#define EE 256
#define HH 8
#define DD 32
#define MM (BB*SS)          // 1024 tokens
#define MAXN 0.99999f       // (1 - 1e-5) / sqrt(C), C = 1
#define EPS15 1e-15f
#define DELTA7 1e-7f

// ---------------- scratch (device globals; no runtime allocation) ----------------
__device__ float g_mx  [MM * 3 * EE];    // qkv GEMM partial (k 0..127)
__device__ float g_mxp [MM * 3 * EE];    // qkv GEMM partial (k 128..255)
__device__ float g_q   [MM * EE];
__device__ float g_k   [MM * EE];
__device__ float g_lv  [MM * EE];        // logmap0(v), per head
__device__ float g_qn  [BB*HH*SS];
__device__ float g_iqn [BB*HH*SS];
__device__ float g_kn  [BB*HH*SS];
__device__ float g_ikn [BB*HH*SS];
__device__ float g_ao  [MM * EE];        // attention output (after expmap0)
__device__ float g_mx2 [MM * EE];        // out-proj partial (k 0..127)
__device__ float g_mx2p[MM * EE];        // out-proj partial (k 128..255)

// ---------------- reductions ----------------
__device__ __forceinline__ float warp_red(float v) {
#pragma unroll
    for (int o = 16; o; o >>= 1) v += __shfl_xor_sync(0xffffffffu, v, o);
    return v;
}
__device__ __forceinline__ float grp4_red(float v) {
    v += __shfl_xor_sync(0xffffffffu, v, 1);
    v += __shfl_xor_sync(0xffffffffu, v, 2);
    return v;
}
__device__ __forceinline__ float dot4(float4 a, float4 b) {
    return a.x*b.x + a.y*b.y + a.z*b.z + a.w*b.w;
}

#define STR_T(buf, r, c, v4) do { \
    (buf)[((c)+0)*68+(r)] = (v4).x; (buf)[((c)+1)*68+(r)] = (v4).y; \
    (buf)[((c)+2)*68+(r)] = (v4).z; (buf)[((c)+3)*68+(r)] = (v4).w; } while (0)

// ---------------- pipelined GEMM: out[r][c] = sum_k A[r][k] * W[c][k] ----------------
// split-K via blockIdx.z: z=0 -> out0 (k base 0), z=1 -> out1 (k base ktiles*32)
__global__ __launch_bounds__(256) void gemm64p(
    const float* __restrict__ A,
    const float* __restrict__ W0, const float* __restrict__ W1, const float* __restrict__ W2,
    float* __restrict__ out0, float* __restrict__ out1, int ldo, int ktiles)
{
    __shared__ __align__(16) float aT[2][32*68];
    __shared__ __align__(16) float wT[2][32*68];
    int r0  = blockIdx.x * 64;
    int cg0 = blockIdx.y * 64;
    int wsel = cg0 >> 8;
    const float* W = (wsel == 0) ? W0 : ((wsel == 1) ? W1 : W2);
    int wc0 = cg0 & 255;
    float* out = (blockIdx.z == 0) ? out0 : out1;
    int kb0 = blockIdx.z * (ktiles * 32);

    int t = threadIdx.x;
    int ty = t >> 4, tx = t & 15;
    int lr0 = t >> 3;            // 0..31
    int lc  = (t & 7) * 4;       // 0,4,..,28
    float acc[4][4] = {};

    // prologue: tile 0 -> buf 0
    {
        float4 a0 = *(const float4*)&A[(r0 + lr0) * 256 + kb0 + lc];
        float4 a1 = *(const float4*)&A[(r0 + lr0 + 32) * 256 + kb0 + lc];
        float4 w0 = *(const float4*)&W[(wc0 + lr0) * 256 + kb0 + lc];
        float4 w1 = *(const float4*)&W[(wc0 + lr0 + 32) * 256 + kb0 + lc];
        STR_T(aT[0], lr0, lc, a0); STR_T(aT[0], lr0 + 32, lc, a1);
        STR_T(wT[0], lr0, lc, w0); STR_T(wT[0], lr0 + 32, lc, w1);
    }
    __syncthreads();

    for (int kt = 0; kt < ktiles; kt++) {
        int cur = kt & 1;
        bool more = (kt + 1) < ktiles;
        float4 a0, a1, w0, w1;
        if (more) {
            int kb = kb0 + (kt + 1) * 32;
            a0 = *(const float4*)&A[(r0 + lr0) * 256 + kb + lc];
            a1 = *(const float4*)&A[(r0 + lr0 + 32) * 256 + kb + lc];
            w0 = *(const float4*)&W[(wc0 + lr0) * 256 + kb + lc];
            w1 = *(const float4*)&W[(wc0 + lr0 + 32) * 256 + kb + lc];
        }
        const float* ac = aT[cur];
        const float* wc = wT[cur];
#pragma unroll
        for (int j = 0; j < 32; j++) {
            float4 a = *(const float4*)&ac[j * 68 + ty * 4];
            float4 b = *(const float4*)&wc[j * 68 + tx * 4];
            float av[4] = {a.x, a.y, a.z, a.w};
            float bv[4] = {b.x, b.y, b.z, b.w};
#pragma unroll
            for (int i = 0; i < 4; i++)
#pragma unroll
                for (int jj = 0; jj < 4; jj++)
                    acc[i][jj] = fmaf(av[i], bv[jj], acc[i][jj]);
        }
        if (more) {
            int nxt = cur ^ 1;
            STR_T(aT[nxt], lr0, lc, a0); STR_T(aT[nxt], lr0 + 32, lc, a1);
            STR_T(wT[nxt], lr0, lc, w0); STR_T(wT[nxt], lr0 + 32, lc, w1);
        }
        __syncthreads();
    }
#pragma unroll
    for (int i = 0; i < 4; i++) {
        float4 v = make_float4(acc[i][0], acc[i][1], acc[i][2], acc[i][3]);
        *(float4*)&out[(r0 + ty * 4 + i) * ldo + cg0 + tx * 4] = v;
    }
}

// ---------------- per-token QKV postprocess: warp-per-token, shfl-only ----------------
__global__ __launch_bounds__(256) void post_qkv_w(
    const float* __restrict__ x,
    const float* __restrict__ bq, const float* __restrict__ bk, const float* __restrict__ bv)
{
    int wid = threadIdx.x >> 5, lane = threadIdx.x & 31;
    int token = blockIdx.x * 8 + wid;

    const float4* xr = (const float4*)(x + token * EE);
    float4 xa = xr[lane * 2], xb = xr[lane * 2 + 1];
    float xn2 = warp_red(dot4(xa, xa) + dot4(xb, xb));
    float xn = sqrtf(fmaxf(xn2, EPS15));
    float at = atanhf(fminf(xn, 1.f - 1e-5f));   // SC = 1

    int b = token >> 9, s = token & 511;
    int h = lane >> 2;
    int hidx = (b * HH + h) * SS + s;

#pragma unroll
    for (int w = 0; w < 3; w++) {
        const float* bvec = (w == 0) ? bq : ((w == 1) ? bk : bv);
        const float4* mr  = (const float4*)(g_mx  + token * (3 * EE) + w * EE);
        const float4* mrp = (const float4*)(g_mxp + token * (3 * EE) + w * EE);
        float4 ma = mr[lane * 2], mb = mr[lane * 2 + 1];
        float4 pa = mrp[lane * 2], pb = mrp[lane * 2 + 1];
        ma.x += pa.x; ma.y += pa.y; ma.z += pa.z; ma.w += pa.w;
        mb.x += pb.x; mb.y += pb.y; mb.z += pb.z; mb.w += pb.w;
        const float4* br = (const float4*)bvec;
        float4 ba = br[lane * 2], bb4 = br[lane * 2 + 1];

        float sm2 = warp_red(dot4(ma, ma) + dot4(mb, mb));
        float mxn = sqrtf(fmaxf(sm2, EPS15));
        float factor = tanhf(mxn / xn * at) / mxn;
        float x2 = factor * factor * sm2;
        float xy = warp_red(factor * (dot4(ma, ba) + dot4(mb, bb4)));
        float y2 = warp_red(dot4(ba, ba) + dot4(bb4, bb4));
        float u  = 1.f + 2.f * xy + y2;
        float idn = 1.f / (1.f + 2.f * xy + x2 * y2 + EPS15);
        float c1 = u * factor;
        float c2 = 1.f - x2;

        float r0 = (c1 * ma.x + c2 * ba.x) * idn;
        float r1 = (c1 * ma.y + c2 * ba.y) * idn;
        float r2 = (c1 * ma.z + c2 * ba.z) * idn;
        float r3 = (c1 * ma.w + c2 * ba.w) * idn;
        float r4 = (c1 * mb.x + c2 * bb4.x) * idn;
        float r5 = (c1 * mb.y + c2 * bb4.y) * idn;
        float r6 = (c1 * mb.z + c2 * bb4.z) * idn;
        float r7 = (c1 * mb.w + c2 * bb4.w) * idn;

        if (w < 2) {
            r0 = fminf(r0, MAXN); r1 = fminf(r1, MAXN); r2 = fminf(r2, MAXN); r3 = fminf(r3, MAXN);
            r4 = fminf(r4, MAXN); r5 = fminf(r5, MAXN); r6 = fminf(r6, MAXN); r7 = fminf(r7, MAXN);
            float hn = grp4_red(r0*r0 + r1*r1 + r2*r2 + r3*r3 + r4*r4 + r5*r5 + r6*r6 + r7*r7);
            float4* dst = (float4*)((w == 0 ? g_q : g_k) + token * EE);
            dst[lane * 2]     = make_float4(r0, r1, r2, r3);
            dst[lane * 2 + 1] = make_float4(r4, r5, r6, r7);
            if ((lane & 3) == 0) {
                if (w == 0) { g_qn[hidx] = hn; g_iqn[hidx] = 1.f / (1.f - hn); }
                else        { g_kn[hidx] = hn; g_ikn[hidx] = 1.f / (1.f - hn); }
            }
        } else {
            float vn2 = grp4_red(r0*r0 + r1*r1 + r2*r2 + r3*r3 + r4*r4 + r5*r5 + r6*r6 + r7*r7);
            float vn = sqrtf(fmaxf(vn2, EPS15));
            float lf = atanhf(fminf(vn, 1.f - 1e-5f)) / vn;
            float4* dst = (float4*)(g_lv + token * EE);
            dst[lane * 2]     = make_float4(lf*r0, lf*r1, lf*r2, lf*r3);
            dst[lane * 2 + 1] = make_float4(lf*r4, lf*r5, lf*r6, lf*r7);
        }
    }
}

// ---------------- fused attention, double-buffered K/lv chunks ----------------
// dynamic smem layout (floats):
//  qT   [32*68]  @ 0      (reused as osS 64x34 at tail)
//  kT0  [32*68]  @ 2176   (reused as rsS 64x17 at tail)
//  kT1  [32*68]  @ 4352
//  lv0  [64*36]  @ 6528
//  lv1  [64*36]  @ 8832
//  wS   [64*68]  @ 11136
//  qns  [64]     @ 15488  (reused as rsF at tail)
//  iqs  [64]     @ 15552
//  kns  [2*64]   @ 15616
//  iks  [2*64]   @ 15744
// total 15872 floats = 63488 bytes
#define ATTN_SMEM_BYTES 63488
__global__ __launch_bounds__(256) void attn_fused(const float* __restrict__ hs)
{
    extern __shared__ __align__(16) float sm[];
    float* qT  = sm;
    float* kTb0 = sm + 2176;
    float* kTb1 = sm + 4352;
    float* lv0  = sm + 6528;
    float* lv1  = sm + 8832;
    float* wS   = sm + 11136;
    float* qns  = sm + 15488;
    float* iqs  = sm + 15552;
    float* kns  = sm + 15616;
    float* iks  = sm + 15744;

    int qt = blockIdx.x, bh = blockIdx.y;
    int b = bh >> 3, h = bh & 7;
    int q0 = qt * 64;
    int t = threadIdx.x;
    int ty = t >> 4, tx = t & 15;     // scores mapping
    int ty2 = t >> 3, tx2 = t & 7;    // AV mapping
    int lr0 = t >> 3;                  // load mapping: rows lr0, lr0+32
    int lc  = (t & 7) * 4;             // cols lc..lc+3

    const float* kbase  = g_k  + (size_t)b * SS * EE + h * DD;
    const float* lvbase = g_lv + (size_t)b * SS * EE + h * DD;

    // prologue: Q tile + chunk 0
    {
        float4 q0v = *(const float4*)&g_q[(b * SS + q0 + lr0) * EE + h * DD + lc];
        float4 q1v = *(const float4*)&g_q[(b * SS + q0 + lr0 + 32) * EE + h * DD + lc];
        STR_T(qT, lr0, lc, q0v); STR_T(qT, lr0 + 32, lc, q1v);
        float4 k0v = *(const float4*)&kbase[lr0 * EE + lc];
        float4 k1v = *(const float4*)&kbase[(lr0 + 32) * EE + lc];
        STR_T(kTb0, lr0, lc, k0v); STR_T(kTb0, lr0 + 32, lc, k1v);
        float4 l0v = *(const float4*)&lvbase[lr0 * EE + lc];
        float4 l1v = *(const float4*)&lvbase[(lr0 + 32) * EE + lc];
        *(float4*)&lv0[lr0 * 36 + lc] = l0v;
        *(float4*)&lv0[(lr0 + 32) * 36 + lc] = l1v;
        if (t < 64) {
            qns[t] = g_qn[bh * SS + q0 + t]; iqs[t] = g_iqn[bh * SS + q0 + t];
            kns[t] = g_kn[bh * SS + t];      iks[t] = g_ikn[bh * SS + t];
        }
    }
    __syncthreads();

    float negcc = -1.f / (hs[h] * 5.656854249f);   // -1/(head_scaling*sqrt(32))
    float av0[4] = {}, av1[4] = {};
    float rs[4] = {};

    for (int c = 0; c < 8; c++) {
        int cur = c & 1;
        bool more = c < 7;
        const float* kT  = cur ? kTb1 : kTb0;
        const float* lvS = cur ? lv1 : lv0;

        // issue LDGs for chunk c+1 (overlap with compute below)
        float4 k0v, k1v, l0v, l1v; float knv = 0.f, ikv0 = 0.f;
        if (more) {
            int c0n = (c + 1) * 64;
            k0v = *(const float4*)&kbase[(c0n + lr0) * EE + lc];
            k1v = *(const float4*)&kbase[(c0n + lr0 + 32) * EE + lc];
            l0v = *(const float4*)&lvbase[(c0n + lr0) * EE + lc];
            l1v = *(const float4*)&lvbase[(c0n + lr0 + 32) * EE + lc];
            if (t < 64) { knv = g_kn[bh * SS + c0n + t]; ikv0 = g_ikn[bh * SS + c0n + t]; }
        }

        // scores GEMM
        float acc[4][4] = {};
#pragma unroll
        for (int j = 0; j < 32; j++) {
            float4 a  = *(const float4*)&qT[j * 68 + ty * 4];
            float4 bb = *(const float4*)&kT[j * 68 + tx * 4];
            float avr[4] = {a.x, a.y, a.z, a.w};
            float bvr[4] = {bb.x, bb.y, bb.z, bb.w};
#pragma unroll
            for (int i = 0; i < 4; i++)
#pragma unroll
                for (int jj = 0; jj < 4; jj++)
                    acc[i][jj] = fmaf(avr[i], bvr[jj], acc[i][jj]);
        }

        // transform -> unnormalized weights + row-sum partials
        float k2v[4], ikv[4], vfv[4], vf2v[4];
#pragma unroll
        for (int j = 0; j < 4; j++) {
            k2v[j] = kns[cur * 64 + tx * 4 + j];
            ikv[j] = iks[cur * 64 + tx * 4 + j];
            vfv[j] = 1.f - k2v[j];
            vf2v[j] = vfv[j] * vfv[j];
        }
#pragma unroll
        for (int i = 0; i < 4; i++) {
            float q2  = qns[ty * 4 + i];
            float iq2 = 2.f * iqs[ty * 4 + i];
#pragma unroll
            for (int j = 0; j < 4; j++) {
                float xy  = -acc[i][j];
                float t0  = fmaf(2.f, xy, 1.f);
                float u   = t0 + q2;
                float den = fmaf(k2v[j], q2, t0);
                float rd  = __fdividef(1.f, den);
                float num2 = fmaf(u * u, k2v[j], vf2v[j] * q2);
                num2 = fmaf(u * vfv[j], xy + xy, num2);
                float dn  = num2 * rd * rd;
                float am1 = fmaxf(dn * (iq2 * ikv[j]), DELTA7);
                float z   = (1.f + am1) + sqrtf(fmaf(am1, am1, am1 + am1));
                float wv  = exp2f(negcc * __log2f(z));
                rs[i] += wv;
                acc[i][j] = wv;
            }
        }
#pragma unroll
        for (int i = 0; i < 4; i++)
            *(float4*)&wS[(ty * 4 + i) * 68 + tx * 4] =
                make_float4(acc[i][0], acc[i][1], acc[i][2], acc[i][3]);

        // stage chunk c+1 into the other buffers (free: last use was before prev sync)
        if (more) {
            int nxt = cur ^ 1;
            float* kTn  = nxt ? kTb1 : kTb0;
            float* lvn  = nxt ? lv1 : lv0;
            STR_T(kTn, lr0, lc, k0v); STR_T(kTn, lr0 + 32, lc, k1v);
            *(float4*)&lvn[lr0 * 36 + lc] = l0v;
            *(float4*)&lvn[(lr0 + 32) * 36 + lc] = l1v;
            if (t < 64) { kns[nxt * 64 + t] = knv; iks[nxt * 64 + t] = ikv0; }
        }
        __syncthreads();   // wS + next-chunk tiles visible

        // AV accumulate
        const float* wp0 = &wS[(ty2 * 2) * 68];
        const float* wp1 = wp0 + 68;
        const float* lp  = &lvS[tx2 * 4];
#pragma unroll 8
        for (int cc = 0; cc < 64; cc += 2) {
            float2 wa = *(const float2*)(wp0 + cc);
            float2 wb = *(const float2*)(wp1 + cc);
            float4 l0 = *(const float4*)(lp + cc * 36);
            float4 l1 = *(const float4*)(lp + (cc + 1) * 36);
            av0[0] = fmaf(wa.x, l0.x, av0[0]); av0[0] = fmaf(wa.y, l1.x, av0[0]);
            av0[1] = fmaf(wa.x, l0.y, av0[1]); av0[1] = fmaf(wa.y, l1.y, av0[1]);
            av0[2] = fmaf(wa.x, l0.z, av0[2]); av0[2] = fmaf(wa.y, l1.z, av0[2]);
            av0[3] = fmaf(wa.x, l0.w, av0[3]); av0[3] = fmaf(wa.y, l1.w, av0[3]);
            av1[0] = fmaf(wb.x, l0.x, av1[0]); av1[0] = fmaf(wb.y, l1.x, av1[0]);
            av1[1] = fmaf(wb.x, l0.y, av1[1]); av1[1] = fmaf(wb.y, l1.y, av1[1]);
            av1[2] = fmaf(wb.x, l0.z, av1[2]); av1[2] = fmaf(wb.y, l1.z, av1[2]);
            av1[3] = fmaf(wb.x, l0.w, av1[3]); av1[3] = fmaf(wb.y, l1.w, av1[3]);
        }
        __syncthreads();   // AV(c) done before chunk c+2 overwrites cur buffers / wS
    }

    // row-sum reduction across 16 tx lanes (reuse kTb0 as 64x17)
    float* rsS = kTb0;
#pragma unroll
    for (int i = 0; i < 4; i++) rsS[(ty * 4 + i) * 17 + tx] = rs[i];
    __syncthreads();
    float* rsF = qns;   // reuse
    if (t < 64) {
        float s = 0.f;
#pragma unroll
        for (int xx = 0; xx < 16; xx++) s += rsS[t * 17 + xx];
        rsF[t] = __fdividef(1.f, s);
    }
    __syncthreads();

    // normalize + stage to osS (reuse qT as 64x34)
    float* osS = qT;
    {
        int qa = ty2 * 2;
        float ir0 = rsF[qa], ir1 = rsF[qa + 1];
        *(float2*)&osS[qa * 34 + tx2 * 4]           = make_float2(av0[0] * ir0, av0[1] * ir0);
        *(float2*)&osS[qa * 34 + tx2 * 4 + 2]       = make_float2(av0[2] * ir0, av0[3] * ir0);
        *(float2*)&osS[(qa + 1) * 34 + tx2 * 4]     = make_float2(av1[0] * ir1, av1[1] * ir1);
        *(float2*)&osS[(qa + 1) * 34 + tx2 * 4 + 2] = make_float2(av1[2] * ir1, av1[3] * ir1);
    }
    __syncthreads();

    // expmap0 per head row (warp over d = 32)
    int wid = t >> 5, lane = t & 31;
#pragma unroll
    for (int rr = 0; rr < 8; rr++) {
        int row = wid * 8 + rr;
        float v = osS[row * 34 + lane];
        float n2 = warp_red(v * v);
        float un = sqrtf(fmaxf(n2, EPS15));
        float f = tanhf(un) / un;   // SC = 1
        g_ao[(b * SS + q0 + row) * EE + h * DD + lane] = f * v;
    }
}

// ---------------- final hyp_linear tail: warp-per-token ----------------
__global__ __launch_bounds__(256) void post_out_w(const float* __restrict__ bo, float* __restrict__ out)
{
    int wid = threadIdx.x >> 5, lane = threadIdx.x & 31;
    int token = blockIdx.x * 8 + wid;

    const float4* xr = (const float4*)(g_ao + token * EE);
    float4 xa = xr[lane * 2], xb = xr[lane * 2 + 1];
    float xn2 = warp_red(dot4(xa, xa) + dot4(xb, xb));
    float xn = sqrtf(fmaxf(xn2, EPS15));
    float at = atanhf(fminf(xn, 1.f - 1e-5f));

    const float4* mr  = (const float4*)(g_mx2  + token * EE);
    const float4* mrp = (const float4*)(g_mx2p + token * EE);
    float4 ma = mr[lane * 2], mb = mr[lane * 2 + 1];
    float4 pa = mrp[lane * 2], pb = mrp[lane * 2 + 1];
    ma.x += pa.x; ma.y += pa.y; ma.z += pa.z; ma.w += pa.w;
    mb.x += pb.x; mb.y += pb.y; mb.z += pb.z; mb.w += pb.w;
    const float4* br = (const float4*)bo;
    float4 ba = br[lane * 2], bb4 = br[lane * 2 + 1];

    float sm2 = warp_red(dot4(ma, ma) + dot4(mb, mb));
    float mxn = sqrtf(fmaxf(sm2, EPS15));
    float factor = tanhf(mxn / xn * at) / mxn;
    float x2 = factor * factor * sm2;
    float xy = warp_red(factor * (dot4(ma, ba) + dot4(mb, bb4)));
    float y2 = warp_red(dot4(ba, ba) + dot4(bb4, bb4));
    float u  = 1.f + 2.f * xy + y2;
    float idn = 1.f / (1.f + 2.f * xy + x2 * y2 + EPS15);
    float c1 = u * factor;
    float c2 = 1.f - x2;

    float4* dst = (float4*)(out + token * EE);
    dst[lane * 2] = make_float4(
        (c1 * ma.x + c2 * ba.x) * idn, (c1 * ma.y + c2 * ba.y) * idn,
        (c1 * ma.z + c2 * ba.z) * idn, (c1 * ma.w + c2 * ba.w) * idn);
    dst[lane * 2 + 1] = make_float4(
        (c1 * mb.x + c2 * bb4.x) * idn, (c1 * mb.y + c2 * bb4.y) * idn,
        (c1 * mb.z + c2 * bb4.z) * idn, (c1 * mb.w + c2 * bb4.w) * idn);
}

// ---------------- launch ----------------
extern "C" void kernel_launch(void* const* d_in, const int* in_sizes, int n_in,
                              void* d_out, int out_size)
{
    const float* x  = (const float*)d_in[0];
    const float* Wq = (const float*)d_in[1];
    const float* bq = (const float*)d_in[2];
    const float* Wk = (const float*)d_in[3];
    const float* bk = (const float*)d_in[4];
    const float* Wv = (const float*)d_in[5];
    const float* bv = (const float*)d_in[6];
    const float* Wo = (const float*)d_in[7];
    const float* bo = (const float*)d_in[8];
    const float* hs = (const float*)d_in[9];
    float* out = (float*)d_out;

    float *mx, *mxp, *mx2, *mx2p, *ao;
    cudaGetSymbolAddress((void**)&mx,   g_mx);
    cudaGetSymbolAddress((void**)&mxp,  g_mxp);
    cudaGetSymbolAddress((void**)&mx2,  g_mx2);
    cudaGetSymbolAddress((void**)&mx2p, g_mx2p);
    cudaGetSymbolAddress((void**)&ao,   g_ao);

    cudaFuncSetAttribute(attn_fused, cudaFuncAttributeMaxDynamicSharedMemorySize, ATTN_SMEM_BYTES);

    gemm64p    <<<dim3(16, 12, 2), 256>>>(x, Wq, Wk, Wv, mx, mxp, 3 * EE, 4);
    post_qkv_w <<<MM / 8, 256>>>(x, bq, bk, bv);
    attn_fused <<<dim3(8, BB * HH), 256, ATTN_SMEM_BYTES>>>(hs);
    gemm64p    <<<dim3(16, 4, 2), 256>>>(ao, Wo, Wo, Wo, mx2, mx2p, EE, 4);
    post_out_w <<<MM / 8, 256>>>(bo, out);
}

// round 9
// speedup vs baseline: 1.3705x; 1.0579x over previous
#include <cuda_runtime.h>
#include <math.h>

// Problem constants
#define BB 2
#define SS 512
#define EE 256
#define HH 8
#define DD 32
#define MM (BB*SS)          // 1024 tokens
#define MAXN 0.99999f       // (1 - 1e-5) / sqrt(C), C = 1
#define EPS15 1e-15f
#define DELTA7 1e-7f

// ---------------- scratch (device globals; no runtime allocation) ----------------
__device__ float g_mx  [MM * 3 * EE];    // qkv GEMM partial (k 0..127)
__device__ float g_mxp [MM * 3 * EE];    // qkv GEMM partial (k 128..255)
__device__ float g_q   [MM * EE];
__device__ float g_k   [MM * EE];
__device__ float g_lv  [MM * EE];        // logmap0(v), per head
__device__ float g_qn  [BB*HH*SS];
__device__ float g_iqn [BB*HH*SS];
__device__ float g_kn  [BB*HH*SS];
__device__ float g_ikn [BB*HH*SS];
__device__ float g_ao  [MM * EE];        // attention output (after expmap0)
__device__ float g_mx2 [MM * EE];        // out-proj partial (k 0..127)
__device__ float g_mx2p[MM * EE];        // out-proj partial (k 128..255)

// ---------------- reductions ----------------
__device__ __forceinline__ float warp_red(float v) {
#pragma unroll
    for (int o = 16; o; o >>= 1) v += __shfl_xor_sync(0xffffffffu, v, o);
    return v;
}
__device__ __forceinline__ float grp4_red(float v) {
    v += __shfl_xor_sync(0xffffffffu, v, 1);
    v += __shfl_xor_sync(0xffffffffu, v, 2);
    return v;
}
__device__ __forceinline__ float dot4(float4 a, float4 b) {
    return a.x*b.x + a.y*b.y + a.z*b.z + a.w*b.w;
}

#define STR_T(buf, r, c, v4) do { \
    (buf)[((c)+0)*68+(r)] = (v4).x; (buf)[((c)+1)*68+(r)] = (v4).y; \
    (buf)[((c)+2)*68+(r)] = (v4).z; (buf)[((c)+3)*68+(r)] = (v4).w; } while (0)

// ---------------- tf32 mma helpers ----------------
__device__ __forceinline__ unsigned tf32h(float x) {
    unsigned r; asm("cvt.rna.tf32.f32 %0, %1;" : "=r"(r) : "f"(x)); return r;
}
__device__ __forceinline__ unsigned tf32lo(float x, unsigned hi) {
    return tf32h(x - __uint_as_float(hi));
}
__device__ __forceinline__ void mma8(float4& d,
    unsigned a0, unsigned a1, unsigned a2, unsigned a3, unsigned b0, unsigned b1)
{
    asm("mma.sync.aligned.m16n8k8.row.col.f32.tf32.tf32.f32 "
        "{%0,%1,%2,%3},{%4,%5,%6,%7},{%8,%9},{%0,%1,%2,%3};"
        : "+f"(d.x), "+f"(d.y), "+f"(d.z), "+f"(d.w)
        : "r"(a0), "r"(a1), "r"(a2), "r"(a3), "r"(b0), "r"(b1));
}

// ---------------- TF32x3 mma GEMM: out[r][c] = sum_k A[r][k] * W[c][k] ----------------
// No smem, no barriers. Warp tile 16x32 (4 n-tiles of m16n8k8). Fragments loaded
// directly from global as float2 via the k-pair permutation:
//   logical k-slot (t%4)     -> physical column 2*(t%4)
//   logical k-slot (t%4)+4   -> physical column 2*(t%4)+1
// (valid for any consistent A/B column permutation since sum over k commutes).
// split-K via blockIdx.z (z=0 -> out0, z=1 -> out1), ksteps k-steps of 8 each.
__global__ __launch_bounds__(256) void gemm_tf32(
    const float* __restrict__ A,
    const float* __restrict__ W0, const float* __restrict__ W1, const float* __restrict__ W2,
    float* __restrict__ out0, float* __restrict__ out1, int ldo, int ksteps)
{
    int r0  = blockIdx.x * 64;
    int cg0 = blockIdx.y * 64;
    int wsel = cg0 >> 8;
    const float* W = (wsel == 0) ? W0 : ((wsel == 1) ? W1 : W2);
    int wc0 = cg0 & 255;
    float* out = (blockIdx.z == 0) ? out0 : out1;
    int kb0 = blockIdx.z * (ksteps * 8);

    int lane = threadIdx.x & 31;
    int wid  = threadIdx.x >> 5;
    int wm = (wid & 3) * 16;    // warp row offset within 64
    int wn = (wid >> 2) * 32;   // warp col offset within 64
    int tq = lane >> 2;         // 0..7
    int tr = lane & 3;          // 0..3

    const float* ap0 = A + (r0 + wm + tq) * 256 + kb0 + 2 * tr;        // row r
    const float* ap1 = ap0 + 8 * 256;                                   // row r+8
    const float* bp  = W + (wc0 + wn + tq) * 256 + kb0 + 2 * tr;       // n-tile base

    float4 acc[4] = {};

#pragma unroll 4
    for (int ks = 0; ks < ksteps; ks++) {
        float2 a0 = *(const float2*)(ap0 + ks * 8);
        float2 a1 = *(const float2*)(ap1 + ks * 8);
        float2 bb[4];
#pragma unroll
        for (int nt = 0; nt < 4; nt++)
            bb[nt] = *(const float2*)(bp + nt * 8 * 256 + ks * 8);

        // A fragment: a0=(r,2c) a1=(r+8,2c) a2=(r,2c+1) a3=(r+8,2c+1)
        unsigned ah0 = tf32h(a0.x), ah1 = tf32h(a1.x), ah2 = tf32h(a0.y), ah3 = tf32h(a1.y);
        unsigned al0 = tf32lo(a0.x, ah0), al1 = tf32lo(a1.x, ah1);
        unsigned al2 = tf32lo(a0.y, ah2), al3 = tf32lo(a1.y, ah3);

#pragma unroll
        for (int nt = 0; nt < 4; nt++) {
            unsigned bh0 = tf32h(bb[nt].x), bh1 = tf32h(bb[nt].y);
            unsigned bl0 = tf32lo(bb[nt].x, bh0), bl1 = tf32lo(bb[nt].y, bh1);
            mma8(acc[nt], ah0, ah1, ah2, ah3, bl0, bl1);   // hi * lo
            mma8(acc[nt], al0, al1, al2, al3, bh0, bh1);   // lo * hi
            mma8(acc[nt], ah0, ah1, ah2, ah3, bh0, bh1);   // hi * hi
        }
    }

    // C layout: c0=(r,2c) c1=(r,2c+1) c2=(r+8,2c) c3=(r+8,2c+1)
    int orow = r0 + wm + tq;
#pragma unroll
    for (int nt = 0; nt < 4; nt++) {
        int oc = cg0 + wn + nt * 8 + 2 * tr;
        *(float2*)&out[orow * ldo + oc]       = make_float2(acc[nt].x, acc[nt].y);
        *(float2*)&out[(orow + 8) * ldo + oc] = make_float2(acc[nt].z, acc[nt].w);
    }
}

// ---------------- per-token QKV postprocess: warp-per-token, shfl-only ----------------
__global__ __launch_bounds__(256) void post_qkv_w(
    const float* __restrict__ x,
    const float* __restrict__ bq, const float* __restrict__ bk, const float* __restrict__ bv)
{
    int wid = threadIdx.x >> 5, lane = threadIdx.x & 31;
    int token = blockIdx.x * 8 + wid;

    const float4* xr = (const float4*)(x + token * EE);
    float4 xa = xr[lane * 2], xb = xr[lane * 2 + 1];
    float xn2 = warp_red(dot4(xa, xa) + dot4(xb, xb));
    float xn = sqrtf(fmaxf(xn2, EPS15));
    float at = atanhf(fminf(xn, 1.f - 1e-5f));   // SC = 1

    int b = token >> 9, s = token & 511;
    int h = lane >> 2;
    int hidx = (b * HH + h) * SS + s;

#pragma unroll
    for (int w = 0; w < 3; w++) {
        const float* bvec = (w == 0) ? bq : ((w == 1) ? bk : bv);
        const float4* mr  = (const float4*)(g_mx  + token * (3 * EE) + w * EE);
        const float4* mrp = (const float4*)(g_mxp + token * (3 * EE) + w * EE);
        float4 ma = mr[lane * 2], mb = mr[lane * 2 + 1];
        float4 pa = mrp[lane * 2], pb = mrp[lane * 2 + 1];
        ma.x += pa.x; ma.y += pa.y; ma.z += pa.z; ma.w += pa.w;
        mb.x += pb.x; mb.y += pb.y; mb.z += pb.z; mb.w += pb.w;
        const float4* br = (const float4*)bvec;
        float4 ba = br[lane * 2], bb4 = br[lane * 2 + 1];

        float sm2 = warp_red(dot4(ma, ma) + dot4(mb, mb));
        float mxn = sqrtf(fmaxf(sm2, EPS15));
        float factor = tanhf(mxn / xn * at) / mxn;
        float x2 = factor * factor * sm2;
        float xy = warp_red(factor * (dot4(ma, ba) + dot4(mb, bb4)));
        float y2 = warp_red(dot4(ba, ba) + dot4(bb4, bb4));
        float u  = 1.f + 2.f * xy + y2;
        float idn = 1.f / (1.f + 2.f * xy + x2 * y2 + EPS15);
        float c1 = u * factor;
        float c2 = 1.f - x2;

        float r0 = (c1 * ma.x + c2 * ba.x) * idn;
        float r1 = (c1 * ma.y + c2 * ba.y) * idn;
        float r2 = (c1 * ma.z + c2 * ba.z) * idn;
        float r3 = (c1 * ma.w + c2 * ba.w) * idn;
        float r4 = (c1 * mb.x + c2 * bb4.x) * idn;
        float r5 = (c1 * mb.y + c2 * bb4.y) * idn;
        float r6 = (c1 * mb.z + c2 * bb4.z) * idn;
        float r7 = (c1 * mb.w + c2 * bb4.w) * idn;

        if (w < 2) {
            r0 = fminf(r0, MAXN); r1 = fminf(r1, MAXN); r2 = fminf(r2, MAXN); r3 = fminf(r3, MAXN);
            r4 = fminf(r4, MAXN); r5 = fminf(r5, MAXN); r6 = fminf(r6, MAXN); r7 = fminf(r7, MAXN);
            float hn = grp4_red(r0*r0 + r1*r1 + r2*r2 + r3*r3 + r4*r4 + r5*r5 + r6*r6 + r7*r7);
            float4* dst = (float4*)((w == 0 ? g_q : g_k) + token * EE);
            dst[lane * 2]     = make_float4(r0, r1, r2, r3);
            dst[lane * 2 + 1] = make_float4(r4, r5, r6, r7);
            if ((lane & 3) == 0) {
                if (w == 0) { g_qn[hidx] = hn; g_iqn[hidx] = 1.f / (1.f - hn); }
                else        { g_kn[hidx] = hn; g_ikn[hidx] = 1.f / (1.f - hn); }
            }
        } else {
            float vn2 = grp4_red(r0*r0 + r1*r1 + r2*r2 + r3*r3 + r4*r4 + r5*r5 + r6*r6 + r7*r7);
            float vn = sqrtf(fmaxf(vn2, EPS15));
            float lf = atanhf(fminf(vn, 1.f - 1e-5f)) / vn;
            float4* dst = (float4*)(g_lv + token * EE);
            dst[lane * 2]     = make_float4(lf*r0, lf*r1, lf*r2, lf*r3);
            dst[lane * 2 + 1] = make_float4(lf*r4, lf*r5, lf*r6, lf*r7);
        }
    }
}

// ---------------- fused attention, double-buffered K/lv chunks ----------------
#define ATTN_SMEM_BYTES 63488
__global__ __launch_bounds__(256) void attn_fused(const float* __restrict__ hs)
{
    extern __shared__ __align__(16) float sm[];
    float* qT  = sm;
    float* kTb0 = sm + 2176;
    float* kTb1 = sm + 4352;
    float* lv0  = sm + 6528;
    float* lv1  = sm + 8832;
    float* wS   = sm + 11136;
    float* qns  = sm + 15488;
    float* iqs  = sm + 15552;
    float* kns  = sm + 15616;
    float* iks  = sm + 15744;

    int qt = blockIdx.x, bh = blockIdx.y;
    int b = bh >> 3, h = bh & 7;
    int q0 = qt * 64;
    int t = threadIdx.x;
    int ty = t >> 4, tx = t & 15;     // scores mapping
    int ty2 = t >> 3, tx2 = t & 7;    // AV mapping
    int lr0 = t >> 3;                  // load mapping: rows lr0, lr0+32
    int lc  = (t & 7) * 4;             // cols lc..lc+3

    const float* kbase  = g_k  + (size_t)b * SS * EE + h * DD;
    const float* lvbase = g_lv + (size_t)b * SS * EE + h * DD;

    // prologue: Q tile + chunk 0
    {
        float4 q0v = *(const float4*)&g_q[(b * SS + q0 + lr0) * EE + h * DD + lc];
        float4 q1v = *(const float4*)&g_q[(b * SS + q0 + lr0 + 32) * EE + h * DD + lc];
        STR_T(qT, lr0, lc, q0v); STR_T(qT, lr0 + 32, lc, q1v);
        float4 k0v = *(const float4*)&kbase[lr0 * EE + lc];
        float4 k1v = *(const float4*)&kbase[(lr0 + 32) * EE + lc];
        STR_T(kTb0, lr0, lc, k0v); STR_T(kTb0, lr0 + 32, lc, k1v);
        float4 l0v = *(const float4*)&lvbase[lr0 * EE + lc];
        float4 l1v = *(const float4*)&lvbase[(lr0 + 32) * EE + lc];
        *(float4*)&lv0[lr0 * 36 + lc] = l0v;
        *(float4*)&lv0[(lr0 + 32) * 36 + lc] = l1v;
        if (t < 64) {
            qns[t] = g_qn[bh * SS + q0 + t]; iqs[t] = g_iqn[bh * SS + q0 + t];
            kns[t] = g_kn[bh * SS + t];      iks[t] = g_ikn[bh * SS + t];
        }
    }
    __syncthreads();

    float negcc = -1.f / (hs[h] * 5.656854249f);   // -1/(head_scaling*sqrt(32))
    float av0[4] = {}, av1[4] = {};
    float rs[4] = {};

    for (int c = 0; c < 8; c++) {
        int cur = c & 1;
        bool more = c < 7;
        const float* kT  = cur ? kTb1 : kTb0;
        const float* lvS = cur ? lv1 : lv0;

        // issue LDGs for chunk c+1 (overlap with compute below)
        float4 k0v, k1v, l0v, l1v; float knv = 0.f, ikv0 = 0.f;
        if (more) {
            int c0n = (c + 1) * 64;
            k0v = *(const float4*)&kbase[(c0n + lr0) * EE + lc];
            k1v = *(const float4*)&kbase[(c0n + lr0 + 32) * EE + lc];
            l0v = *(const float4*)&lvbase[(c0n + lr0) * EE + lc];
            l1v = *(const float4*)&lvbase[(c0n + lr0 + 32) * EE + lc];
            if (t < 64) { knv = g_kn[bh * SS + c0n + t]; ikv0 = g_ikn[bh * SS + c0n + t]; }
        }

        // scores GEMM
        float acc[4][4] = {};
#pragma unroll
        for (int j = 0; j < 32; j++) {
            float4 a  = *(const float4*)&qT[j * 68 + ty * 4];
            float4 bb = *(const float4*)&kT[j * 68 + tx * 4];
            float avr[4] = {a.x, a.y, a.z, a.w};
            float bvr[4] = {bb.x, bb.y, bb.z, bb.w};
#pragma unroll
            for (int i = 0; i < 4; i++)
#pragma unroll
                for (int jj = 0; jj < 4; jj++)
                    acc[i][jj] = fmaf(avr[i], bvr[jj], acc[i][jj]);
        }

        // transform -> unnormalized weights + row-sum partials
        float k2v[4], ikv[4], vfv[4], vf2v[4];
#pragma unroll
        for (int j = 0; j < 4; j++) {
            k2v[j] = kns[cur * 64 + tx * 4 + j];
            ikv[j] = iks[cur * 64 + tx * 4 + j];
            vfv[j] = 1.f - k2v[j];
            vf2v[j] = vfv[j] * vfv[j];
        }
#pragma unroll
        for (int i = 0; i < 4; i++) {
            float q2  = qns[ty * 4 + i];
            float iq2 = 2.f * iqs[ty * 4 + i];
#pragma unroll
            for (int j = 0; j < 4; j++) {
                float xy  = -acc[i][j];
                float t0  = fmaf(2.f, xy, 1.f);
                float u   = t0 + q2;
                float den = fmaf(k2v[j], q2, t0);
                float rd  = __fdividef(1.f, den);
                float num2 = fmaf(u * u, k2v[j], vf2v[j] * q2);
                num2 = fmaf(u * vfv[j], xy + xy, num2);
                float dn  = num2 * rd * rd;
                float am1 = fmaxf(dn * (iq2 * ikv[j]), DELTA7);
                float z   = (1.f + am1) + sqrtf(fmaf(am1, am1, am1 + am1));
                float wv  = exp2f(negcc * __log2f(z));
                rs[i] += wv;
                acc[i][j] = wv;
            }
        }
#pragma unroll
        for (int i = 0; i < 4; i++)
            *(float4*)&wS[(ty * 4 + i) * 68 + tx * 4] =
                make_float4(acc[i][0], acc[i][1], acc[i][2], acc[i][3]);

        // stage chunk c+1 into the other buffers
        if (more) {
            int nxt = cur ^ 1;
            float* kTn  = nxt ? kTb1 : kTb0;
            float* lvn  = nxt ? lv1 : lv0;
            STR_T(kTn, lr0, lc, k0v); STR_T(kTn, lr0 + 32, lc, k1v);
            *(float4*)&lvn[lr0 * 36 + lc] = l0v;
            *(float4*)&lvn[(lr0 + 32) * 36 + lc] = l1v;
            if (t < 64) { kns[nxt * 64 + t] = knv; iks[nxt * 64 + t] = ikv0; }
        }
        __syncthreads();   // wS + next-chunk tiles visible

        // AV accumulate
        const float* wp0 = &wS[(ty2 * 2) * 68];
        const float* wp1 = wp0 + 68;
        const float* lp  = &lvS[tx2 * 4];
#pragma unroll 8
        for (int cc = 0; cc < 64; cc += 2) {
            float2 wa = *(const float2*)(wp0 + cc);
            float2 wb = *(const float2*)(wp1 + cc);
            float4 l0 = *(const float4*)(lp + cc * 36);
            float4 l1 = *(const float4*)(lp + (cc + 1) * 36);
            av0[0] = fmaf(wa.x, l0.x, av0[0]); av0[0] = fmaf(wa.y, l1.x, av0[0]);
            av0[1] = fmaf(wa.x, l0.y, av0[1]); av0[1] = fmaf(wa.y, l1.y, av0[1]);
            av0[2] = fmaf(wa.x, l0.z, av0[2]); av0[2] = fmaf(wa.y, l1.z, av0[2]);
            av0[3] = fmaf(wa.x, l0.w, av0[3]); av0[3] = fmaf(wa.y, l1.w, av0[3]);
            av1[0] = fmaf(wb.x, l0.x, av1[0]); av1[0] = fmaf(wb.y, l1.x, av1[0]);
            av1[1] = fmaf(wb.x, l0.y, av1[1]); av1[1] = fmaf(wb.y, l1.y, av1[1]);
            av1[2] = fmaf(wb.x, l0.z, av1[2]); av1[2] = fmaf(wb.y, l1.z, av1[2]);
            av1[3] = fmaf(wb.x, l0.w, av1[3]); av1[3] = fmaf(wb.y, l1.w, av1[3]);
        }
        __syncthreads();   // AV(c) done before chunk c+2 overwrites cur buffers / wS
    }

    // row-sum reduction across 16 tx lanes (reuse kTb0 as 64x17)
    float* rsS = kTb0;
#pragma unroll
    for (int i = 0; i < 4; i++) rsS[(ty * 4 + i) * 17 + tx] = rs[i];
    __syncthreads();
    float* rsF = qns;   // reuse
    if (t < 64) {
        float s = 0.f;
#pragma unroll
        for (int xx = 0; xx < 16; xx++) s += rsS[t * 17 + xx];
        rsF[t] = __fdividef(1.f, s);
    }
    __syncthreads();

    // normalize + stage to osS (reuse qT as 64x34)
    float* osS = qT;
    {
        int qa = ty2 * 2;
        float ir0 = rsF[qa], ir1 = rsF[qa + 1];
        *(float2*)&osS[qa * 34 + tx2 * 4]           = make_float2(av0[0] * ir0, av0[1] * ir0);
        *(float2*)&osS[qa * 34 + tx2 * 4 + 2]       = make_float2(av0[2] * ir0, av0[3] * ir0);
        *(float2*)&osS[(qa + 1) * 34 + tx2 * 4]     = make_float2(av1[0] * ir1, av1[1] * ir1);
        *(float2*)&osS[(qa + 1) * 34 + tx2 * 4 + 2] = make_float2(av1[2] * ir1, av1[3] * ir1);
    }
    __syncthreads();

    // expmap0 per head row (warp over d = 32)
    int wid = t >> 5, lane = t & 31;
#pragma unroll
    for (int rr = 0; rr < 8; rr++) {
        int row = wid * 8 + rr;
        float v = osS[row * 34 + lane];
        float n2 = warp_red(v * v);
        float un = sqrtf(fmaxf(n2, EPS15));
        float f = tanhf(un) / un;   // SC = 1
        g_ao[(b * SS + q0 + row) * EE + h * DD + lane] = f * v;
    }
}

// ---------------- final hyp_linear tail: warp-per-token ----------------
__global__ __launch_bounds__(256) void post_out_w(const float* __restrict__ bo, float* __restrict__ out)
{
    int wid = threadIdx.x >> 5, lane = threadIdx.x & 31;
    int token = blockIdx.x * 8 + wid;

    const float4* xr = (const float4*)(g_ao + token * EE);
    float4 xa = xr[lane * 2], xb = xr[lane * 2 + 1];
    float xn2 = warp_red(dot4(xa, xa) + dot4(xb, xb));
    float xn = sqrtf(fmaxf(xn2, EPS15));
    float at = atanhf(fminf(xn, 1.f - 1e-5f));

    const float4* mr  = (const float4*)(g_mx2  + token * EE);
    const float4* mrp = (const float4*)(g_mx2p + token * EE);
    float4 ma = mr[lane * 2], mb = mr[lane * 2 + 1];
    float4 pa = mrp[lane * 2], pb = mrp[lane * 2 + 1];
    ma.x += pa.x; ma.y += pa.y; ma.z += pa.z; ma.w += pa.w;
    mb.x += pb.x; mb.y += pb.y; mb.z += pb.z; mb.w += pb.w;
    const float4* br = (const float4*)bo;
    float4 ba = br[lane * 2], bb4 = br[lane * 2 + 1];

    float sm2 = warp_red(dot4(ma, ma) + dot4(mb, mb));
    float mxn = sqrtf(fmaxf(sm2, EPS15));
    float factor = tanhf(mxn / xn * at) / mxn;
    float x2 = factor * factor * sm2;
    float xy = warp_red(factor * (dot4(ma, ba) + dot4(mb, bb4)));
    float y2 = warp_red(dot4(ba, ba) + dot4(bb4, bb4));
    float u  = 1.f + 2.f * xy + y2;
    float idn = 1.f / (1.f + 2.f * xy + x2 * y2 + EPS15);
    float c1 = u * factor;
    float c2 = 1.f - x2;

    float4* dst = (float4*)(out + token * EE);
    dst[lane * 2] = make_float4(
        (c1 * ma.x + c2 * ba.x) * idn, (c1 * ma.y + c2 * ba.y) * idn,
        (c1 * ma.z + c2 * ba.z) * idn, (c1 * ma.w + c2 * ba.w) * idn);
    dst[lane * 2 + 1] = make_float4(
        (c1 * mb.x + c2 * bb4.x) * idn, (c1 * mb.y + c2 * bb4.y) * idn,
        (c1 * mb.z + c2 * bb4.z) * idn, (c1 * mb.w + c2 * bb4.w) * idn);
}

// ---------------- launch ----------------
extern "C" void kernel_launch(void* const* d_in, const int* in_sizes, int n_in,
                              void* d_out, int out_size)
{
    const float* x  = (const float*)d_in[0];
    const float* Wq = (const float*)d_in[1];
    const float* bq = (const float*)d_in[2];
    const float* Wk = (const float*)d_in[3];
    const float* bk = (const float*)d_in[4];
    const float* Wv = (const float*)d_in[5];
    const float* bv = (const float*)d_in[6];
    const float* Wo = (const float*)d_in[7];
    const float* bo = (const float*)d_in[8];
    const float* hs = (const float*)d_in[9];
    float* out = (float*)d_out;

    float *mx, *mxp, *mx2, *mx2p, *ao;
    cudaGetSymbolAddress((void**)&mx,   g_mx);
    cudaGetSymbolAddress((void**)&mxp,  g_mxp);
    cudaGetSymbolAddress((void**)&mx2,  g_mx2);
    cudaGetSymbolAddress((void**)&mx2p, g_mx2p);
    cudaGetSymbolAddress((void**)&ao,   g_ao);

    cudaFuncSetAttribute(attn_fused, cudaFuncAttributeMaxDynamicSharedMemorySize, ATTN_SMEM_BYTES);

    gemm_tf32  <<<dim3(16, 12, 2), 256>>>(x, Wq, Wk, Wv, mx, mxp, 3 * EE, 16);
    post_qkv_w <<<MM / 8, 256>>>(x, bq, bk, bv);
    attn_fused <<<dim3(8, BB * HH), 256, ATTN_SMEM_BYTES>>>(hs);
    gemm_tf32  <<<dim3(16, 4, 2), 256>>>(ao, Wo, Wo, Wo, mx2, mx2p, EE, 16);
    post_out_w <<<MM / 8, 256>>>(bo, out);
}

// round 11
// speedup vs baseline: 1.5245x; 1.1124x over previous
#include <cuda_runtime.h>
#include <math.h>

// Problem constants
#define BB 2
#define SS 512
#define EE 256
#define HH 8
#define DD 32
#define MM (BB*SS)          // 1024 tokens
#define MAXN 0.99999f       // (1 - 1e-5) / sqrt(C), C = 1
#define EPS15 1e-15f
#define DELTA7 1e-7f

// ---------------- scratch (device globals; no runtime allocation) ----------------
__device__ float g_p0 [MM * 3 * EE];     // qkv GEMM partials (split-K 4)
__device__ float g_p1 [MM * 3 * EE];
__device__ float g_p2 [MM * 3 * EE];
__device__ float g_p3 [MM * 3 * EE];
__device__ float g_q  [MM * EE];
__device__ float g_k  [MM * EE];
__device__ float g_lv [MM * EE];         // logmap0(v), per head
__device__ float g_qn [BB*HH*SS];
__device__ float g_iqn[BB*HH*SS];
__device__ float g_kn [BB*HH*SS];
__device__ float g_ikn[BB*HH*SS];
__device__ float g_avp[4 * BB*HH * SS * DD];  // AV partials per key-split
__device__ float g_rsp[4 * BB*HH * SS];       // row-sum partials per key-split
__device__ float g_ao [MM * EE];         // attention output (after expmap0)
__device__ float g_o0 [MM * EE];         // out-proj partials (split-K 4)
__device__ float g_o1 [MM * EE];
__device__ float g_o2 [MM * EE];
__device__ float g_o3 [MM * EE];

// ---------------- reductions ----------------
__device__ __forceinline__ float warp_red(float v) {
#pragma unroll
    for (int o = 16; o; o >>= 1) v += __shfl_xor_sync(0xffffffffu, v, o);
    return v;
}
__device__ __forceinline__ float grp4_red(float v) {
    v += __shfl_xor_sync(0xffffffffu, v, 1);
    v += __shfl_xor_sync(0xffffffffu, v, 2);
    return v;
}
__device__ __forceinline__ float dot4(float4 a, float4 b) {
    return a.x*b.x + a.y*b.y + a.z*b.z + a.w*b.w;
}

#define STR_T(buf, r, c, v4) do { \
    (buf)[((c)+0)*68+(r)] = (v4).x; (buf)[((c)+1)*68+(r)] = (v4).y; \
    (buf)[((c)+2)*68+(r)] = (v4).z; (buf)[((c)+3)*68+(r)] = (v4).w; } while (0)

// ---------------- tf32 mma helpers ----------------
__device__ __forceinline__ unsigned tf32h(float x) {
    unsigned r; asm("cvt.rna.tf32.f32 %0, %1;" : "=r"(r) : "f"(x)); return r;
}
__device__ __forceinline__ unsigned tf32lo(float x, unsigned hi) {
    return tf32h(x - __uint_as_float(hi));
}
__device__ __forceinline__ void mma8(float4& d,
    unsigned a0, unsigned a1, unsigned a2, unsigned a3, unsigned b0, unsigned b1)
{
    asm("mma.sync.aligned.m16n8k8.row.col.f32.tf32.tf32.f32 "
        "{%0,%1,%2,%3},{%4,%5,%6,%7},{%8,%9},{%0,%1,%2,%3};"
        : "+f"(d.x), "+f"(d.y), "+f"(d.z), "+f"(d.w)
        : "r"(a0), "r"(a1), "r"(a2), "r"(a3), "r"(b0), "r"(b1));
}

// ---------------- TF32x3 mma GEMM, split-K 4, fully unrolled k loop ----------------
// out[r][c] = sum_k A[r][k] * W[c][k]; warp tile 16x32; k-pair permutation
// (logical k-slots {c, c+4} -> physical columns {2c, 2c+1}).
// Each split-z covers k range [z*KSTEPS*8, (z+1)*KSTEPS*8). KSTEPS=8 with 4 splits
// covers K=256 exactly.
template<int KSTEPS>
__global__ __launch_bounds__(256) void gemm_tf32(
    const float* __restrict__ A,
    const float* __restrict__ W0, const float* __restrict__ W1, const float* __restrict__ W2,
    float* __restrict__ o0, float* __restrict__ o1,
    float* __restrict__ o2, float* __restrict__ o3, int ldo)
{
    int r0  = blockIdx.x * 64;
    int cg0 = blockIdx.y * 64;
    int wsel = cg0 >> 8;
    const float* W = (wsel == 0) ? W0 : ((wsel == 1) ? W1 : W2);
    int wc0 = cg0 & 255;
    int z = blockIdx.z;
    float* out = (z == 0) ? o0 : (z == 1) ? o1 : (z == 2) ? o2 : o3;
    int kb0 = z * (KSTEPS * 8);

    int lane = threadIdx.x & 31;
    int wid  = threadIdx.x >> 5;
    int wm = (wid & 3) * 16;
    int wn = (wid >> 2) * 32;
    int tq = lane >> 2;
    int tr = lane & 3;

    const float* ap0 = A + (r0 + wm + tq) * 256 + kb0 + 2 * tr;
    const float* ap1 = ap0 + 8 * 256;
    const float* bp  = W + (wc0 + wn + tq) * 256 + kb0 + 2 * tr;

    float4 acc[4] = {};

    // prologue loads for ks=0
    float2 a0c = *(const float2*)ap0;
    float2 a1c = *(const float2*)ap1;
    float2 bbc[4];
#pragma unroll
    for (int nt = 0; nt < 4; nt++) bbc[nt] = *(const float2*)(bp + nt * 8 * 256);

#pragma unroll
    for (int ks = 0; ks < KSTEPS; ks++) {
        float2 a0n, a1n, bbn[4];
        if (ks + 1 < KSTEPS) {
            a0n = *(const float2*)(ap0 + (ks + 1) * 8);
            a1n = *(const float2*)(ap1 + (ks + 1) * 8);
#pragma unroll
            for (int nt = 0; nt < 4; nt++)
                bbn[nt] = *(const float2*)(bp + nt * 8 * 256 + (ks + 1) * 8);
        }

        unsigned ah0 = tf32h(a0c.x), ah1 = tf32h(a1c.x), ah2 = tf32h(a0c.y), ah3 = tf32h(a1c.y);
        unsigned al0 = tf32lo(a0c.x, ah0), al1 = tf32lo(a1c.x, ah1);
        unsigned al2 = tf32lo(a0c.y, ah2), al3 = tf32lo(a1c.y, ah3);

#pragma unroll
        for (int nt = 0; nt < 4; nt++) {
            unsigned bh0 = tf32h(bbc[nt].x), bh1 = tf32h(bbc[nt].y);
            unsigned bl0 = tf32lo(bbc[nt].x, bh0), bl1 = tf32lo(bbc[nt].y, bh1);
            mma8(acc[nt], ah0, ah1, ah2, ah3, bl0, bl1);
            mma8(acc[nt], al0, al1, al2, al3, bh0, bh1);
            mma8(acc[nt], ah0, ah1, ah2, ah3, bh0, bh1);
        }
        if (ks + 1 < KSTEPS) {
            a0c = a0n; a1c = a1n;
#pragma unroll
            for (int nt = 0; nt < 4; nt++) bbc[nt] = bbn[nt];
        }
    }

    int orow = r0 + wm + tq;
#pragma unroll
    for (int nt = 0; nt < 4; nt++) {
        int oc = cg0 + wn + nt * 8 + 2 * tr;
        *(float2*)&out[orow * ldo + oc]       = make_float2(acc[nt].x, acc[nt].y);
        *(float2*)&out[(orow + 8) * ldo + oc] = make_float2(acc[nt].z, acc[nt].w);
    }
}

// ---------------- per-token QKV postprocess: warp-per-token, shfl-only ----------------
__global__ __launch_bounds__(256) void post_qkv_w(
    const float* __restrict__ x,
    const float* __restrict__ bq, const float* __restrict__ bk, const float* __restrict__ bv)
{
    int wid = threadIdx.x >> 5, lane = threadIdx.x & 31;
    int token = blockIdx.x * 8 + wid;

    const float4* xr = (const float4*)(x + token * EE);
    float4 xa = xr[lane * 2], xb = xr[lane * 2 + 1];
    float xn2 = warp_red(dot4(xa, xa) + dot4(xb, xb));
    float xn = sqrtf(fmaxf(xn2, EPS15));
    float at = atanhf(fminf(xn, 1.f - 1e-5f));   // SC = 1

    int b = token >> 9, s = token & 511;
    int h = lane >> 2;
    int hidx = (b * HH + h) * SS + s;

#pragma unroll
    for (int w = 0; w < 3; w++) {
        const float* bvec = (w == 0) ? bq : ((w == 1) ? bk : bv);
        size_t off = (size_t)token * (3 * EE) + w * EE;
        const float4* m0 = (const float4*)(g_p0 + off);
        const float4* m1 = (const float4*)(g_p1 + off);
        const float4* m2 = (const float4*)(g_p2 + off);
        const float4* m3 = (const float4*)(g_p3 + off);
        float4 ma = m0[lane*2], mb = m0[lane*2+1];
        float4 t1a = m1[lane*2], t1b = m1[lane*2+1];
        float4 t2a = m2[lane*2], t2b = m2[lane*2+1];
        float4 t3a = m3[lane*2], t3b = m3[lane*2+1];
        ma.x += t1a.x + t2a.x + t3a.x; ma.y += t1a.y + t2a.y + t3a.y;
        ma.z += t1a.z + t2a.z + t3a.z; ma.w += t1a.w + t2a.w + t3a.w;
        mb.x += t1b.x + t2b.x + t3b.x; mb.y += t1b.y + t2b.y + t3b.y;
        mb.z += t1b.z + t2b.z + t3b.z; mb.w += t1b.w + t2b.w + t3b.w;

        const float4* br = (const float4*)bvec;
        float4 ba = br[lane * 2], bb4 = br[lane * 2 + 1];

        float sm2 = warp_red(dot4(ma, ma) + dot4(mb, mb));
        float mxn = sqrtf(fmaxf(sm2, EPS15));
        float factor = tanhf(mxn / xn * at) / mxn;
        float x2 = factor * factor * sm2;
        float xy = warp_red(factor * (dot4(ma, ba) + dot4(mb, bb4)));
        float y2 = warp_red(dot4(ba, ba) + dot4(bb4, bb4));
        float u  = 1.f + 2.f * xy + y2;
        float idn = 1.f / (1.f + 2.f * xy + x2 * y2 + EPS15);
        float c1 = u * factor;
        float c2 = 1.f - x2;

        float r0 = (c1 * ma.x + c2 * ba.x) * idn;
        float r1 = (c1 * ma.y + c2 * ba.y) * idn;
        float r2 = (c1 * ma.z + c2 * ba.z) * idn;
        float r3 = (c1 * ma.w + c2 * ba.w) * idn;
        float r4 = (c1 * mb.x + c2 * bb4.x) * idn;
        float r5 = (c1 * mb.y + c2 * bb4.y) * idn;
        float r6 = (c1 * mb.z + c2 * bb4.z) * idn;
        float r7 = (c1 * mb.w + c2 * bb4.w) * idn;

        if (w < 2) {
            r0 = fminf(r0, MAXN); r1 = fminf(r1, MAXN); r2 = fminf(r2, MAXN); r3 = fminf(r3, MAXN);
            r4 = fminf(r4, MAXN); r5 = fminf(r5, MAXN); r6 = fminf(r6, MAXN); r7 = fminf(r7, MAXN);
            float hn = grp4_red(r0*r0 + r1*r1 + r2*r2 + r3*r3 + r4*r4 + r5*r5 + r6*r6 + r7*r7);
            float4* dst = (float4*)((w == 0 ? g_q : g_k) + token * EE);
            dst[lane * 2]     = make_float4(r0, r1, r2, r3);
            dst[lane * 2 + 1] = make_float4(r4, r5, r6, r7);
            if ((lane & 3) == 0) {
                if (w == 0) { g_qn[hidx] = hn; g_iqn[hidx] = 1.f / (1.f - hn); }
                else        { g_kn[hidx] = hn; g_ikn[hidx] = 1.f / (1.f - hn); }
            }
        } else {
            float vn2 = grp4_red(r0*r0 + r1*r1 + r2*r2 + r3*r3 + r4*r4 + r5*r5 + r6*r6 + r7*r7);
            float vn = sqrtf(fmaxf(vn2, EPS15));
            float lf = atanhf(fminf(vn, 1.f - 1e-5f)) / vn;
            float4* dst = (float4*)(g_lv + token * EE);
            dst[lane * 2]     = make_float4(lf*r0, lf*r1, lf*r2, lf*r3);
            dst[lane * 2 + 1] = make_float4(lf*r4, lf*r5, lf*r6, lf*r7);
        }
    }
}

// ---------------- fused attention, 4-way key split (2 chunks per CTA) ----------------
#define ATTN_SMEM_BYTES 63488
__global__ __launch_bounds__(256) void attn_fused(const float* __restrict__ hs)
{
    extern __shared__ __align__(16) float sm[];
    float* qT  = sm;
    float* kTb0 = sm + 2176;
    float* kTb1 = sm + 4352;
    float* lv0  = sm + 6528;
    float* lv1  = sm + 8832;
    float* wS   = sm + 11136;
    float* qns  = sm + 15488;
    float* iqs  = sm + 15552;
    float* kns  = sm + 15616;
    float* iks  = sm + 15744;

    int qt = blockIdx.x, sp = blockIdx.y, bh = blockIdx.z;
    int b = bh >> 3, h = bh & 7;
    int q0 = qt * 64;
    int cbase = sp * 128;             // this CTA handles keys [cbase, cbase+128)
    int t = threadIdx.x;
    int ty = t >> 4, tx = t & 15;     // scores mapping
    int ty2 = t >> 3, tx2 = t & 7;    // AV mapping
    int lr0 = t >> 3;
    int lc  = (t & 7) * 4;

    const float* kbase  = g_k  + (size_t)b * SS * EE + h * DD;
    const float* lvbase = g_lv + (size_t)b * SS * EE + h * DD;

    // prologue: Q tile + first chunk
    {
        float4 q0v = *(const float4*)&g_q[(b * SS + q0 + lr0) * EE + h * DD + lc];
        float4 q1v = *(const float4*)&g_q[(b * SS + q0 + lr0 + 32) * EE + h * DD + lc];
        STR_T(qT, lr0, lc, q0v); STR_T(qT, lr0 + 32, lc, q1v);
        float4 k0v = *(const float4*)&kbase[(cbase + lr0) * EE + lc];
        float4 k1v = *(const float4*)&kbase[(cbase + lr0 + 32) * EE + lc];
        STR_T(kTb0, lr0, lc, k0v); STR_T(kTb0, lr0 + 32, lc, k1v);
        float4 l0v = *(const float4*)&lvbase[(cbase + lr0) * EE + lc];
        float4 l1v = *(const float4*)&lvbase[(cbase + lr0 + 32) * EE + lc];
        *(float4*)&lv0[lr0 * 36 + lc] = l0v;
        *(float4*)&lv0[(lr0 + 32) * 36 + lc] = l1v;
        if (t < 64) {
            qns[t] = g_qn[bh * SS + q0 + t]; iqs[t] = g_iqn[bh * SS + q0 + t];
            kns[t] = g_kn[bh * SS + cbase + t]; iks[t] = g_ikn[bh * SS + cbase + t];
        }
    }
    __syncthreads();

    float negcc = -1.f / (hs[h] * 5.656854249f);
    float av0[4] = {}, av1[4] = {};
    float rs[4] = {};

#pragma unroll
    for (int c = 0; c < 2; c++) {
        int cur = c;
        bool more = (c == 0);
        const float* kT  = cur ? kTb1 : kTb0;
        const float* lvS = cur ? lv1 : lv0;

        float4 k0v, k1v, l0v, l1v; float knv = 0.f, ikv0 = 0.f;
        if (more) {
            int c0n = cbase + 64;
            k0v = *(const float4*)&kbase[(c0n + lr0) * EE + lc];
            k1v = *(const float4*)&kbase[(c0n + lr0 + 32) * EE + lc];
            l0v = *(const float4*)&lvbase[(c0n + lr0) * EE + lc];
            l1v = *(const float4*)&lvbase[(c0n + lr0 + 32) * EE + lc];
            if (t < 64) { knv = g_kn[bh * SS + c0n + t]; ikv0 = g_ikn[bh * SS + c0n + t]; }
        }

        // scores GEMM
        float acc[4][4] = {};
#pragma unroll
        for (int j = 0; j < 32; j++) {
            float4 a  = *(const float4*)&qT[j * 68 + ty * 4];
            float4 bb = *(const float4*)&kT[j * 68 + tx * 4];
            float avr[4] = {a.x, a.y, a.z, a.w};
            float bvr[4] = {bb.x, bb.y, bb.z, bb.w};
#pragma unroll
            for (int i = 0; i < 4; i++)
#pragma unroll
                for (int jj = 0; jj < 4; jj++)
                    acc[i][jj] = fmaf(avr[i], bvr[jj], acc[i][jj]);
        }

        // transform -> unnormalized weights + row-sum partials
        float k2v[4], ikv[4], vfv[4], vf2v[4];
#pragma unroll
        for (int j = 0; j < 4; j++) {
            k2v[j] = kns[cur * 64 + tx * 4 + j];
            ikv[j] = iks[cur * 64 + tx * 4 + j];
            vfv[j] = 1.f - k2v[j];
            vf2v[j] = vfv[j] * vfv[j];
        }
#pragma unroll
        for (int i = 0; i < 4; i++) {
            float q2  = qns[ty * 4 + i];
            float iq2 = 2.f * iqs[ty * 4 + i];
#pragma unroll
            for (int j = 0; j < 4; j++) {
                float xy  = -acc[i][j];
                float t0  = fmaf(2.f, xy, 1.f);
                float u   = t0 + q2;
                float den = fmaf(k2v[j], q2, t0);
                float rd  = __fdividef(1.f, den);
                float num2 = fmaf(u * u, k2v[j], vf2v[j] * q2);
                num2 = fmaf(u * vfv[j], xy + xy, num2);
                float dn  = num2 * rd * rd;
                float am1 = fmaxf(dn * (iq2 * ikv[j]), DELTA7);
                float z   = (1.f + am1) + sqrtf(fmaf(am1, am1, am1 + am1));
                float wv  = exp2f(negcc * __log2f(z));
                rs[i] += wv;
                acc[i][j] = wv;
            }
        }
#pragma unroll
        for (int i = 0; i < 4; i++)
            *(float4*)&wS[(ty * 4 + i) * 68 + tx * 4] =
                make_float4(acc[i][0], acc[i][1], acc[i][2], acc[i][3]);

        if (more) {
            STR_T(kTb1, lr0, lc, k0v); STR_T(kTb1, lr0 + 32, lc, k1v);
            *(float4*)&lv1[lr0 * 36 + lc] = l0v;
            *(float4*)&lv1[(lr0 + 32) * 36 + lc] = l1v;
            if (t < 64) { kns[64 + t] = knv; iks[64 + t] = ikv0; }
        }
        __syncthreads();   // wS + next-chunk tiles visible

        // AV accumulate
        const float* wp0 = &wS[(ty2 * 2) * 68];
        const float* wp1 = wp0 + 68;
        const float* lp  = &lvS[tx2 * 4];
#pragma unroll 8
        for (int cc = 0; cc < 64; cc += 2) {
            float2 wa = *(const float2*)(wp0 + cc);
            float2 wb = *(const float2*)(wp1 + cc);
            float4 l0 = *(const float4*)(lp + cc * 36);
            float4 l1 = *(const float4*)(lp + (cc + 1) * 36);
            av0[0] = fmaf(wa.x, l0.x, av0[0]); av0[0] = fmaf(wa.y, l1.x, av0[0]);
            av0[1] = fmaf(wa.x, l0.y, av0[1]); av0[1] = fmaf(wa.y, l1.y, av0[1]);
            av0[2] = fmaf(wa.x, l0.z, av0[2]); av0[2] = fmaf(wa.y, l1.z, av0[2]);
            av0[3] = fmaf(wa.x, l0.w, av0[3]); av0[3] = fmaf(wa.y, l1.w, av0[3]);
            av1[0] = fmaf(wb.x, l0.x, av1[0]); av1[0] = fmaf(wb.y, l1.x, av1[0]);
            av1[1] = fmaf(wb.x, l0.y, av1[1]); av1[1] = fmaf(wb.y, l1.y, av1[1]);
            av1[2] = fmaf(wb.x, l0.z, av1[2]); av1[2] = fmaf(wb.y, l1.z, av1[2]);
            av1[3] = fmaf(wb.x, l0.w, av1[3]); av1[3] = fmaf(wb.y, l1.w, av1[3]);
        }
        __syncthreads();
    }

    // row-sum reduction across 16 tx lanes (reuse kTb0 as 64x17)
    float* rsS = kTb0;
#pragma unroll
    for (int i = 0; i < 4; i++) rsS[(ty * 4 + i) * 17 + tx] = rs[i];
    __syncthreads();
    if (t < 64) {
        float s = 0.f;
#pragma unroll
        for (int xx = 0; xx < 16; xx++) s += rsS[t * 17 + xx];
        g_rsp[(sp * 16 + bh) * SS + q0 + t] = s;
    }

    // store AV partials (unnormalized)
    {
        size_t base = ((size_t)(sp * 16 + bh) * SS + q0 + 2 * ty2) * DD + tx2 * 4;
        *(float4*)&g_avp[base]      = make_float4(av0[0], av0[1], av0[2], av0[3]);
        *(float4*)&g_avp[base + DD] = make_float4(av1[0], av1[1], av1[2], av1[3]);
    }
}

// ---------------- combine key-split partials: normalize + expmap0 ----------------
__global__ __launch_bounds__(256) void attn_combine()
{
    int wid = threadIdx.x >> 5, lane = threadIdx.x & 31;
    int row = blockIdx.x * 8 + wid;       // 0..8191 = bh*512 + q
    int bh = row >> 9, q = row & 511;
    int b = bh >> 3, h = bh & 7;

    float v = 0.f, s = 0.f;
#pragma unroll
    for (int sp = 0; sp < 4; sp++) {
        v += g_avp[((size_t)(sp * 16 + bh) * SS + q) * DD + lane];
        s += g_rsp[(sp * 16 + bh) * SS + q];
    }
    float y = v * __fdividef(1.f, s);
    float n2 = warp_red(y * y);
    float un = sqrtf(fmaxf(n2, EPS15));
    float f = tanhf(un) / un;   // SC = 1
    g_ao[(b * SS + q) * EE + h * DD + lane] = f * y;
}

// ---------------- final hyp_linear tail: warp-per-token ----------------
__global__ __launch_bounds__(256) void post_out_w(const float* __restrict__ bo, float* __restrict__ out)
{
    int wid = threadIdx.x >> 5, lane = threadIdx.x & 31;
    int token = blockIdx.x * 8 + wid;

    const float4* xr = (const float4*)(g_ao + token * EE);
    float4 xa = xr[lane * 2], xb = xr[lane * 2 + 1];
    float xn2 = warp_red(dot4(xa, xa) + dot4(xb, xb));
    float xn = sqrtf(fmaxf(xn2, EPS15));
    float at = atanhf(fminf(xn, 1.f - 1e-5f));

    size_t off = (size_t)token * EE;
    const float4* m0 = (const float4*)(g_o0 + off);
    const float4* m1 = (const float4*)(g_o1 + off);
    const float4* m2 = (const float4*)(g_o2 + off);
    const float4* m3 = (const float4*)(g_o3 + off);
    float4 ma = m0[lane*2], mb = m0[lane*2+1];
    float4 t1a = m1[lane*2], t1b = m1[lane*2+1];
    float4 t2a = m2[lane*2], t2b = m2[lane*2+1];
    float4 t3a = m3[lane*2], t3b = m3[lane*2+1];
    ma.x += t1a.x + t2a.x + t3a.x; ma.y += t1a.y + t2a.y + t3a.y;
    ma.z += t1a.z + t2a.z + t3a.z; ma.w += t1a.w + t2a.w + t3a.w;
    mb.x += t1b.x + t2b.x + t3b.x; mb.y += t1b.y + t2b.y + t3b.y;
    mb.z += t1b.z + t2b.z + t3b.z; mb.w += t1b.w + t2b.w + t3b.w;

    const float4* br = (const float4*)bo;
    float4 ba = br[lane * 2], bb4 = br[lane * 2 + 1];

    float sm2 = warp_red(dot4(ma, ma) + dot4(mb, mb));
    float mxn = sqrtf(fmaxf(sm2, EPS15));
    float factor = tanhf(mxn / xn * at) / mxn;
    float x2 = factor * factor * sm2;
    float xy = warp_red(factor * (dot4(ma, ba) + dot4(mb, bb4)));
    float y2 = warp_red(dot4(ba, ba) + dot4(bb4, bb4));
    float u  = 1.f + 2.f * xy + y2;
    float idn = 1.f / (1.f + 2.f * xy + x2 * y2 + EPS15);
    float c1 = u * factor;
    float c2 = 1.f - x2;

    float4* dst = (float4*)(out + token * EE);
    dst[lane * 2] = make_float4(
        (c1 * ma.x + c2 * ba.x) * idn, (c1 * ma.y + c2 * ba.y) * idn,
        (c1 * ma.z + c2 * ba.z) * idn, (c1 * ma.w + c2 * ba.w) * idn);
    dst[lane * 2 + 1] = make_float4(
        (c1 * mb.x + c2 * bb4.x) * idn, (c1 * mb.y + c2 * bb4.y) * idn,
        (c1 * mb.z + c2 * bb4.z) * idn, (c1 * mb.w + c2 * bb4.w) * idn);
}

// ---------------- launch ----------------
extern "C" void kernel_launch(void* const* d_in, const int* in_sizes, int n_in,
                              void* d_out, int out_size)
{
    const float* x  = (const float*)d_in[0];
    const float* Wq = (const float*)d_in[1];
    const float* bq = (const float*)d_in[2];
    const float* Wk = (const float*)d_in[3];
    const float* bk = (const float*)d_in[4];
    const float* Wv = (const float*)d_in[5];
    const float* bv = (const float*)d_in[6];
    const float* Wo = (const float*)d_in[7];
    const float* bo = (const float*)d_in[8];
    const float* hs = (const float*)d_in[9];
    float* out = (float*)d_out;

    float *p0, *p1, *p2, *p3, *o0, *o1, *o2, *o3, *ao;
    cudaGetSymbolAddress((void**)&p0, g_p0);
    cudaGetSymbolAddress((void**)&p1, g_p1);
    cudaGetSymbolAddress((void**)&p2, g_p2);
    cudaGetSymbolAddress((void**)&p3, g_p3);
    cudaGetSymbolAddress((void**)&o0, g_o0);
    cudaGetSymbolAddress((void**)&o1, g_o1);
    cudaGetSymbolAddress((void**)&o2, g_o2);
    cudaGetSymbolAddress((void**)&o3, g_o3);
    cudaGetSymbolAddress((void**)&ao, g_ao);

    cudaFuncSetAttribute(attn_fused, cudaFuncAttributeMaxDynamicSharedMemorySize, ATTN_SMEM_BYTES);

    // QKV: 4 splits x 8 ksteps x 8 = 256 k-columns. Out-proj: same (was the R10 bug: <4> only covered 128).
    gemm_tf32<8> <<<dim3(16, 12, 4), 256>>>(x, Wq, Wk, Wv, p0, p1, p2, p3, 3 * EE);
    post_qkv_w   <<<MM / 8, 256>>>(x, bq, bk, bv);
    attn_fused   <<<dim3(8, 4, BB * HH), 256, ATTN_SMEM_BYTES>>>(hs);
    attn_combine <<<(BB * HH * SS) / 8, 256>>>();
    gemm_tf32<8> <<<dim3(16, 4, 4), 256>>>(ao, Wo, Wo, Wo, o0, o1, o2, o3, EE);
    post_out_w   <<<MM / 8, 256>>>(bo, out);
}

// round 12
// speedup vs baseline: 1.5820x; 1.0377x over previous
#include <cuda_runtime.h>
#include <math.h>

// Problem constants
#define BB 2
#define SS 512
#define EE 256
#define HH 8
#define DD 32
#define MM (BB*SS)          // 1024 tokens
#define MAXN 0.99999f       // (1 - 1e-5) / sqrt(C), C = 1
#define EPS15 1e-15f
#define DELTA7 1e-7f

// ---------------- scratch (device globals; no runtime allocation) ----------------
__device__ float g_p0 [MM * 3 * EE];     // qkv GEMM partials (split-K 4)
__device__ float g_p1 [MM * 3 * EE];
__device__ float g_p2 [MM * 3 * EE];
__device__ float g_p3 [MM * 3 * EE];
__device__ float g_q  [MM * EE];
__device__ float g_k  [MM * EE];
__device__ float g_lv [MM * EE];         // logmap0(v), per head
__device__ float g_qn [BB*HH*SS];
__device__ float g_iqn[BB*HH*SS];
__device__ float g_kn [BB*HH*SS];
__device__ float g_ikn[BB*HH*SS];
__device__ float g_avp[4 * BB*HH * SS * DD];  // AV partials per key-split
__device__ float g_rsp[4 * BB*HH * SS];       // row-sum partials per key-split
__device__ float g_ao [MM * EE];         // attention output (after expmap0)
__device__ float g_o0 [MM * EE];         // out-proj partials (split-K 4)
__device__ float g_o1 [MM * EE];
__device__ float g_o2 [MM * EE];
__device__ float g_o3 [MM * EE];

// ---------------- PDL primitives ----------------
__device__ __forceinline__ void pdl_wait()    { asm volatile("griddepcontrol.wait;" ::: "memory"); }
__device__ __forceinline__ void pdl_trigger() { asm volatile("griddepcontrol.launch_dependents;" ::: "memory"); }

// ---------------- reductions ----------------
__device__ __forceinline__ float warp_red(float v) {
#pragma unroll
    for (int o = 16; o; o >>= 1) v += __shfl_xor_sync(0xffffffffu, v, o);
    return v;
}
__device__ __forceinline__ float grp4_red(float v) {
    v += __shfl_xor_sync(0xffffffffu, v, 1);
    v += __shfl_xor_sync(0xffffffffu, v, 2);
    return v;
}
__device__ __forceinline__ float dot4(float4 a, float4 b) {
    return a.x*b.x + a.y*b.y + a.z*b.z + a.w*b.w;
}

#define STR_T(buf, r, c, v4) do { \
    (buf)[((c)+0)*68+(r)] = (v4).x; (buf)[((c)+1)*68+(r)] = (v4).y; \
    (buf)[((c)+2)*68+(r)] = (v4).z; (buf)[((c)+3)*68+(r)] = (v4).w; } while (0)

// ---------------- tf32 mma helpers ----------------
__device__ __forceinline__ unsigned tf32h(float x) {
    unsigned r; asm("cvt.rna.tf32.f32 %0, %1;" : "=r"(r) : "f"(x)); return r;
}
__device__ __forceinline__ unsigned tf32lo(float x, unsigned hi) {
    return tf32h(x - __uint_as_float(hi));
}
__device__ __forceinline__ void mma8(float4& d,
    unsigned a0, unsigned a1, unsigned a2, unsigned a3, unsigned b0, unsigned b1)
{
    asm("mma.sync.aligned.m16n8k8.row.col.f32.tf32.tf32.f32 "
        "{%0,%1,%2,%3},{%4,%5,%6,%7},{%8,%9},{%0,%1,%2,%3};"
        : "+f"(d.x), "+f"(d.y), "+f"(d.z), "+f"(d.w)
        : "r"(a0), "r"(a1), "r"(a2), "r"(a3), "r"(b0), "r"(b1));
}

// ---------------- TF32x3 mma GEMM, split-K 4, fully unrolled k loop ----------------
// out[r][c] = sum_k A[r][k] * W[c][k]; warp tile 16x32; k-pair permutation
// (logical k-slots {c, c+4} -> physical columns {2c, 2c+1}).
// Each split-z covers k range [z*KSTEPS*8, (z+1)*KSTEPS*8). KSTEPS=8 x 4 splits = K=256.
template<int KSTEPS>
__global__ __launch_bounds__(256) void gemm_tf32(
    const float* __restrict__ A,
    const float* __restrict__ W0, const float* __restrict__ W1, const float* __restrict__ W2,
    float* __restrict__ o0, float* __restrict__ o1,
    float* __restrict__ o2, float* __restrict__ o3, int ldo)
{
    int r0  = blockIdx.x * 64;
    int cg0 = blockIdx.y * 64;
    int wsel = cg0 >> 8;
    const float* W = (wsel == 0) ? W0 : ((wsel == 1) ? W1 : W2);
    int wc0 = cg0 & 255;
    int z = blockIdx.z;
    float* out = (z == 0) ? o0 : (z == 1) ? o1 : (z == 2) ? o2 : o3;
    int kb0 = z * (KSTEPS * 8);

    int lane = threadIdx.x & 31;
    int wid  = threadIdx.x >> 5;
    int wm = (wid & 3) * 16;
    int wn = (wid >> 2) * 32;
    int tq = lane >> 2;
    int tr = lane & 3;

    const float* ap0 = A + (r0 + wm + tq) * 256 + kb0 + 2 * tr;
    const float* ap1 = ap0 + 8 * 256;
    const float* bp  = W + (wc0 + wn + tq) * 256 + kb0 + 2 * tr;

    // upstream data (A may be produced by predecessor) — wait before first load
    pdl_wait();

    float4 acc[4] = {};

    // prologue loads for ks=0
    float2 a0c = *(const float2*)ap0;
    float2 a1c = *(const float2*)ap1;
    float2 bbc[4];
#pragma unroll
    for (int nt = 0; nt < 4; nt++) bbc[nt] = *(const float2*)(bp + nt * 8 * 256);

#pragma unroll
    for (int ks = 0; ks < KSTEPS; ks++) {
        float2 a0n, a1n, bbn[4];
        if (ks + 1 < KSTEPS) {
            a0n = *(const float2*)(ap0 + (ks + 1) * 8);
            a1n = *(const float2*)(ap1 + (ks + 1) * 8);
#pragma unroll
            for (int nt = 0; nt < 4; nt++)
                bbn[nt] = *(const float2*)(bp + nt * 8 * 256 + (ks + 1) * 8);
        }

        unsigned ah0 = tf32h(a0c.x), ah1 = tf32h(a1c.x), ah2 = tf32h(a0c.y), ah3 = tf32h(a1c.y);
        unsigned al0 = tf32lo(a0c.x, ah0), al1 = tf32lo(a1c.x, ah1);
        unsigned al2 = tf32lo(a0c.y, ah2), al3 = tf32lo(a1c.y, ah3);

#pragma unroll
        for (int nt = 0; nt < 4; nt++) {
            unsigned bh0 = tf32h(bbc[nt].x), bh1 = tf32h(bbc[nt].y);
            unsigned bl0 = tf32lo(bbc[nt].x, bh0), bl1 = tf32lo(bbc[nt].y, bh1);
            mma8(acc[nt], ah0, ah1, ah2, ah3, bl0, bl1);
            mma8(acc[nt], al0, al1, al2, al3, bh0, bh1);
            mma8(acc[nt], ah0, ah1, ah2, ah3, bh0, bh1);
        }
        if (ks + 1 < KSTEPS) {
            a0c = a0n; a1c = a1n;
#pragma unroll
            for (int nt = 0; nt < 4; nt++) bbc[nt] = bbn[nt];
        }
    }

    int orow = r0 + wm + tq;
#pragma unroll
    for (int nt = 0; nt < 4; nt++) {
        int oc = cg0 + wn + nt * 8 + 2 * tr;
        *(float2*)&out[orow * ldo + oc]       = make_float2(acc[nt].x, acc[nt].y);
        *(float2*)&out[(orow + 8) * ldo + oc] = make_float2(acc[nt].z, acc[nt].w);
    }
    pdl_trigger();
}

// ---------------- per-token QKV postprocess: warp-per-token, shfl-only ----------------
__global__ __launch_bounds__(256) void post_qkv_w(
    const float* __restrict__ x,
    const float* __restrict__ bq, const float* __restrict__ bk, const float* __restrict__ bv)
{
    int wid = threadIdx.x >> 5, lane = threadIdx.x & 31;
    int token = blockIdx.x * 8 + wid;

    // x and biases are external inputs — load before waiting on the GEMM
    const float4* xr = (const float4*)(x + token * EE);
    float4 xa = xr[lane * 2], xb = xr[lane * 2 + 1];
    float xn2 = warp_red(dot4(xa, xa) + dot4(xb, xb));
    float xn = sqrtf(fmaxf(xn2, EPS15));
    float at = atanhf(fminf(xn, 1.f - 1e-5f));   // SC = 1

    int b = token >> 9, s = token & 511;
    int h = lane >> 2;
    int hidx = (b * HH + h) * SS + s;

    pdl_wait();   // GEMM partials ready

#pragma unroll
    for (int w = 0; w < 3; w++) {
        const float* bvec = (w == 0) ? bq : ((w == 1) ? bk : bv);
        size_t off = (size_t)token * (3 * EE) + w * EE;
        const float4* m0 = (const float4*)(g_p0 + off);
        const float4* m1 = (const float4*)(g_p1 + off);
        const float4* m2 = (const float4*)(g_p2 + off);
        const float4* m3 = (const float4*)(g_p3 + off);
        float4 ma = m0[lane*2], mb = m0[lane*2+1];
        float4 t1a = m1[lane*2], t1b = m1[lane*2+1];
        float4 t2a = m2[lane*2], t2b = m2[lane*2+1];
        float4 t3a = m3[lane*2], t3b = m3[lane*2+1];
        ma.x += t1a.x + t2a.x + t3a.x; ma.y += t1a.y + t2a.y + t3a.y;
        ma.z += t1a.z + t2a.z + t3a.z; ma.w += t1a.w + t2a.w + t3a.w;
        mb.x += t1b.x + t2b.x + t3b.x; mb.y += t1b.y + t2b.y + t3b.y;
        mb.z += t1b.z + t2b.z + t3b.z; mb.w += t1b.w + t2b.w + t3b.w;

        const float4* br = (const float4*)bvec;
        float4 ba = br[lane * 2], bb4 = br[lane * 2 + 1];

        float sm2 = warp_red(dot4(ma, ma) + dot4(mb, mb));
        float mxn = sqrtf(fmaxf(sm2, EPS15));
        float factor = tanhf(mxn / xn * at) / mxn;
        float x2 = factor * factor * sm2;
        float xy = warp_red(factor * (dot4(ma, ba) + dot4(mb, bb4)));
        float y2 = warp_red(dot4(ba, ba) + dot4(bb4, bb4));
        float u  = 1.f + 2.f * xy + y2;
        float idn = 1.f / (1.f + 2.f * xy + x2 * y2 + EPS15);
        float c1 = u * factor;
        float c2 = 1.f - x2;

        float r0 = (c1 * ma.x + c2 * ba.x) * idn;
        float r1 = (c1 * ma.y + c2 * ba.y) * idn;
        float r2 = (c1 * ma.z + c2 * ba.z) * idn;
        float r3 = (c1 * ma.w + c2 * ba.w) * idn;
        float r4 = (c1 * mb.x + c2 * bb4.x) * idn;
        float r5 = (c1 * mb.y + c2 * bb4.y) * idn;
        float r6 = (c1 * mb.z + c2 * bb4.z) * idn;
        float r7 = (c1 * mb.w + c2 * bb4.w) * idn;

        if (w < 2) {
            r0 = fminf(r0, MAXN); r1 = fminf(r1, MAXN); r2 = fminf(r2, MAXN); r3 = fminf(r3, MAXN);
            r4 = fminf(r4, MAXN); r5 = fminf(r5, MAXN); r6 = fminf(r6, MAXN); r7 = fminf(r7, MAXN);
            float hn = grp4_red(r0*r0 + r1*r1 + r2*r2 + r3*r3 + r4*r4 + r5*r5 + r6*r6 + r7*r7);
            float4* dst = (float4*)((w == 0 ? g_q : g_k) + token * EE);
            dst[lane * 2]     = make_float4(r0, r1, r2, r3);
            dst[lane * 2 + 1] = make_float4(r4, r5, r6, r7);
            if ((lane & 3) == 0) {
                if (w == 0) { g_qn[hidx] = hn; g_iqn[hidx] = 1.f / (1.f - hn); }
                else        { g_kn[hidx] = hn; g_ikn[hidx] = 1.f / (1.f - hn); }
            }
        } else {
            float vn2 = grp4_red(r0*r0 + r1*r1 + r2*r2 + r3*r3 + r4*r4 + r5*r5 + r6*r6 + r7*r7);
            float vn = sqrtf(fmaxf(vn2, EPS15));
            float lf = atanhf(fminf(vn, 1.f - 1e-5f)) / vn;
            float4* dst = (float4*)(g_lv + token * EE);
            dst[lane * 2]     = make_float4(lf*r0, lf*r1, lf*r2, lf*r3);
            dst[lane * 2 + 1] = make_float4(lf*r4, lf*r5, lf*r6, lf*r7);
        }
    }
    pdl_trigger();
}

// ---------------- fused attention, 4-way key split (2 chunks per CTA) ----------------
#define ATTN_SMEM_BYTES 63488
__global__ __launch_bounds__(256) void attn_fused(const float* __restrict__ hs)
{
    extern __shared__ __align__(16) float sm[];
    float* qT  = sm;
    float* kTb0 = sm + 2176;
    float* kTb1 = sm + 4352;
    float* lv0  = sm + 6528;
    float* lv1  = sm + 8832;
    float* wS   = sm + 11136;
    float* qns  = sm + 15488;
    float* iqs  = sm + 15552;
    float* kns  = sm + 15616;
    float* iks  = sm + 15744;

    int qt = blockIdx.x, sp = blockIdx.y, bh = blockIdx.z;
    int b = bh >> 3, h = bh & 7;
    int q0 = qt * 64;
    int cbase = sp * 128;             // this CTA handles keys [cbase, cbase+128)
    int t = threadIdx.x;
    int ty = t >> 4, tx = t & 15;     // scores mapping
    int ty2 = t >> 3, tx2 = t & 7;    // AV mapping
    int lr0 = t >> 3;
    int lc  = (t & 7) * 4;

    const float* kbase  = g_k  + (size_t)b * SS * EE + h * DD;
    const float* lvbase = g_lv + (size_t)b * SS * EE + h * DD;

    float negcc;
    {
        pdl_wait();   // q/k/lv/norms ready
        negcc = -1.f / (hs[h] * 5.656854249f);
    }

    // prologue: Q tile + first chunk
    {
        float4 q0v = *(const float4*)&g_q[(b * SS + q0 + lr0) * EE + h * DD + lc];
        float4 q1v = *(const float4*)&g_q[(b * SS + q0 + lr0 + 32) * EE + h * DD + lc];
        STR_T(qT, lr0, lc, q0v); STR_T(qT, lr0 + 32, lc, q1v);
        float4 k0v = *(const float4*)&kbase[(cbase + lr0) * EE + lc];
        float4 k1v = *(const float4*)&kbase[(cbase + lr0 + 32) * EE + lc];
        STR_T(kTb0, lr0, lc, k0v); STR_T(kTb0, lr0 + 32, lc, k1v);
        float4 l0v = *(const float4*)&lvbase[(cbase + lr0) * EE + lc];
        float4 l1v = *(const float4*)&lvbase[(cbase + lr0 + 32) * EE + lc];
        *(float4*)&lv0[lr0 * 36 + lc] = l0v;
        *(float4*)&lv0[(lr0 + 32) * 36 + lc] = l1v;
        if (t < 64) {
            qns[t] = g_qn[bh * SS + q0 + t]; iqs[t] = g_iqn[bh * SS + q0 + t];
            kns[t] = g_kn[bh * SS + cbase + t]; iks[t] = g_ikn[bh * SS + cbase + t];
        }
    }
    __syncthreads();

    float av0[4] = {}, av1[4] = {};
    float rs[4] = {};

#pragma unroll
    for (int c = 0; c < 2; c++) {
        int cur = c;
        bool more = (c == 0);
        const float* kT  = cur ? kTb1 : kTb0;
        const float* lvS = cur ? lv1 : lv0;

        float4 k0v, k1v, l0v, l1v; float knv = 0.f, ikv0 = 0.f;
        if (more) {
            int c0n = cbase + 64;
            k0v = *(const float4*)&kbase[(c0n + lr0) * EE + lc];
            k1v = *(const float4*)&kbase[(c0n + lr0 + 32) * EE + lc];
            l0v = *(const float4*)&lvbase[(c0n + lr0) * EE + lc];
            l1v = *(const float4*)&lvbase[(c0n + lr0 + 32) * EE + lc];
            if (t < 64) { knv = g_kn[bh * SS + c0n + t]; ikv0 = g_ikn[bh * SS + c0n + t]; }
        }

        // scores GEMM
        float acc[4][4] = {};
#pragma unroll
        for (int j = 0; j < 32; j++) {
            float4 a  = *(const float4*)&qT[j * 68 + ty * 4];
            float4 bb = *(const float4*)&kT[j * 68 + tx * 4];
            float avr[4] = {a.x, a.y, a.z, a.w};
            float bvr[4] = {bb.x, bb.y, bb.z, bb.w};
#pragma unroll
            for (int i = 0; i < 4; i++)
#pragma unroll
                for (int jj = 0; jj < 4; jj++)
                    acc[i][jj] = fmaf(avr[i], bvr[jj], acc[i][jj]);
        }

        // transform -> unnormalized weights + row-sum partials
        float k2v[4], ikv[4], vfv[4], vf2v[4];
#pragma unroll
        for (int j = 0; j < 4; j++) {
            k2v[j] = kns[cur * 64 + tx * 4 + j];
            ikv[j] = iks[cur * 64 + tx * 4 + j];
            vfv[j] = 1.f - k2v[j];
            vf2v[j] = vfv[j] * vfv[j];
        }
#pragma unroll
        for (int i = 0; i < 4; i++) {
            float q2  = qns[ty * 4 + i];
            float iq2 = 2.f * iqs[ty * 4 + i];
#pragma unroll
            for (int j = 0; j < 4; j++) {
                float xy  = -acc[i][j];
                float t0  = fmaf(2.f, xy, 1.f);
                float u   = t0 + q2;
                float den = fmaf(k2v[j], q2, t0);
                float rd  = __fdividef(1.f, den);
                float num2 = fmaf(u * u, k2v[j], vf2v[j] * q2);
                num2 = fmaf(u * vfv[j], xy + xy, num2);
                float dn  = num2 * rd * rd;
                float am1 = fmaxf(dn * (iq2 * ikv[j]), DELTA7);
                float z   = (1.f + am1) + sqrtf(fmaf(am1, am1, am1 + am1));
                float wv  = exp2f(negcc * __log2f(z));
                rs[i] += wv;
                acc[i][j] = wv;
            }
        }
#pragma unroll
        for (int i = 0; i < 4; i++)
            *(float4*)&wS[(ty * 4 + i) * 68 + tx * 4] =
                make_float4(acc[i][0], acc[i][1], acc[i][2], acc[i][3]);

        if (more) {
            STR_T(kTb1, lr0, lc, k0v); STR_T(kTb1, lr0 + 32, lc, k1v);
            *(float4*)&lv1[lr0 * 36 + lc] = l0v;
            *(float4*)&lv1[(lr0 + 32) * 36 + lc] = l1v;
            if (t < 64) { kns[64 + t] = knv; iks[64 + t] = ikv0; }
        }
        __syncthreads();   // wS + next-chunk tiles visible

        // AV accumulate
        const float* wp0 = &wS[(ty2 * 2) * 68];
        const float* wp1 = wp0 + 68;
        const float* lp  = &lvS[tx2 * 4];
#pragma unroll 8
        for (int cc = 0; cc < 64; cc += 2) {
            float2 wa = *(const float2*)(wp0 + cc);
            float2 wb = *(const float2*)(wp1 + cc);
            float4 l0 = *(const float4*)(lp + cc * 36);
            float4 l1 = *(const float4*)(lp + (cc + 1) * 36);
            av0[0] = fmaf(wa.x, l0.x, av0[0]); av0[0] = fmaf(wa.y, l1.x, av0[0]);
            av0[1] = fmaf(wa.x, l0.y, av0[1]); av0[1] = fmaf(wa.y, l1.y, av0[1]);
            av0[2] = fmaf(wa.x, l0.z, av0[2]); av0[2] = fmaf(wa.y, l1.z, av0[2]);
            av0[3] = fmaf(wa.x, l0.w, av0[3]); av0[3] = fmaf(wa.y, l1.w, av0[3]);
            av1[0] = fmaf(wb.x, l0.x, av1[0]); av1[0] = fmaf(wb.y, l1.x, av1[0]);
            av1[1] = fmaf(wb.x, l0.y, av1[1]); av1[1] = fmaf(wb.y, l1.y, av1[1]);
            av1[2] = fmaf(wb.x, l0.z, av1[2]); av1[2] = fmaf(wb.y, l1.z, av1[2]);
            av1[3] = fmaf(wb.x, l0.w, av1[3]); av1[3] = fmaf(wb.y, l1.w, av1[3]);
        }
        __syncthreads();
    }

    // row-sum reduction across 16 tx lanes (reuse kTb0 as 64x17)
    float* rsS = kTb0;
#pragma unroll
    for (int i = 0; i < 4; i++) rsS[(ty * 4 + i) * 17 + tx] = rs[i];
    __syncthreads();
    if (t < 64) {
        float s = 0.f;
#pragma unroll
        for (int xx = 0; xx < 16; xx++) s += rsS[t * 17 + xx];
        g_rsp[(sp * 16 + bh) * SS + q0 + t] = s;
    }

    // store AV partials (unnormalized)
    {
        size_t base = ((size_t)(sp * 16 + bh) * SS + q0 + 2 * ty2) * DD + tx2 * 4;
        *(float4*)&g_avp[base]      = make_float4(av0[0], av0[1], av0[2], av0[3]);
        *(float4*)&g_avp[base + DD] = make_float4(av1[0], av1[1], av1[2], av1[3]);
    }
    pdl_trigger();
}

// ---------------- combine key-split partials: normalize + expmap0 ----------------
__global__ __launch_bounds__(256) void attn_combine()
{
    int wid = threadIdx.x >> 5, lane = threadIdx.x & 31;
    int row = blockIdx.x * 8 + wid;       // 0..8191 = bh*512 + q
    int bh = row >> 9, q = row & 511;
    int b = bh >> 3, h = bh & 7;

    pdl_wait();

    float v = 0.f, s = 0.f;
#pragma unroll
    for (int sp = 0; sp < 4; sp++) {
        v += g_avp[((size_t)(sp * 16 + bh) * SS + q) * DD + lane];
        s += g_rsp[(sp * 16 + bh) * SS + q];
    }
    float y = v * __fdividef(1.f, s);
    float n2 = warp_red(y * y);
    float un = sqrtf(fmaxf(n2, EPS15));
    float f = tanhf(un) / un;   // SC = 1
    g_ao[(b * SS + q) * EE + h * DD + lane] = f * y;
    pdl_trigger();
}

// ---------------- final hyp_linear tail: warp-per-token ----------------
__global__ __launch_bounds__(256) void post_out_w(const float* __restrict__ bo, float* __restrict__ out)
{
    int wid = threadIdx.x >> 5, lane = threadIdx.x & 31;
    int token = blockIdx.x * 8 + wid;

    pdl_wait();

    const float4* xr = (const float4*)(g_ao + token * EE);
    float4 xa = xr[lane * 2], xb = xr[lane * 2 + 1];
    float xn2 = warp_red(dot4(xa, xa) + dot4(xb, xb));
    float xn = sqrtf(fmaxf(xn2, EPS15));
    float at = atanhf(fminf(xn, 1.f - 1e-5f));

    size_t off = (size_t)token * EE;
    const float4* m0 = (const float4*)(g_o0 + off);
    const float4* m1 = (const float4*)(g_o1 + off);
    const float4* m2 = (const float4*)(g_o2 + off);
    const float4* m3 = (const float4*)(g_o3 + off);
    float4 ma = m0[lane*2], mb = m0[lane*2+1];
    float4 t1a = m1[lane*2], t1b = m1[lane*2+1];
    float4 t2a = m2[lane*2], t2b = m2[lane*2+1];
    float4 t3a = m3[lane*2], t3b = m3[lane*2+1];
    ma.x += t1a.x + t2a.x + t3a.x; ma.y += t1a.y + t2a.y + t3a.y;
    ma.z += t1a.z + t2a.z + t3a.z; ma.w += t1a.w + t2a.w + t3a.w;
    mb.x += t1b.x + t2b.x + t3b.x; mb.y += t1b.y + t2b.y + t3b.y;
    mb.z += t1b.z + t2b.z + t3b.z; mb.w += t1b.w + t2b.w + t3b.w;

    const float4* br = (const float4*)bo;
    float4 ba = br[lane * 2], bb4 = br[lane * 2 + 1];

    float sm2 = warp_red(dot4(ma, ma) + dot4(mb, mb));
    float mxn = sqrtf(fmaxf(sm2, EPS15));
    float factor = tanhf(mxn / xn * at) / mxn;
    float x2 = factor * factor * sm2;
    float xy = warp_red(factor * (dot4(ma, ba) + dot4(mb, bb4)));
    float y2 = warp_red(dot4(ba, ba) + dot4(bb4, bb4));
    float u  = 1.f + 2.f * xy + y2;
    float idn = 1.f / (1.f + 2.f * xy + x2 * y2 + EPS15);
    float c1 = u * factor;
    float c2 = 1.f - x2;

    float4* dst = (float4*)(out + token * EE);
    dst[lane * 2] = make_float4(
        (c1 * ma.x + c2 * ba.x) * idn, (c1 * ma.y + c2 * ba.y) * idn,
        (c1 * ma.z + c2 * ba.z) * idn, (c1 * ma.w + c2 * ba.w) * idn);
    dst[lane * 2 + 1] = make_float4(
        (c1 * mb.x + c2 * bb4.x) * idn, (c1 * mb.y + c2 * bb4.y) * idn,
        (c1 * mb.z + c2 * bb4.z) * idn, (c1 * mb.w + c2 * bb4.w) * idn);
}

// ---------------- launch (all kernels chained with PDL) ----------------
template<typename K, typename... Args>
static void launch_pdl(K kern, dim3 grid, dim3 block, size_t smem, Args... args)
{
    cudaLaunchConfig_t cfg = {};
    cfg.gridDim = grid;
    cfg.blockDim = block;
    cfg.dynamicSmemBytes = smem;
    cfg.stream = 0;
    cudaLaunchAttribute at[1];
    at[0].id = cudaLaunchAttributeProgrammaticStreamSerialization;
    at[0].val.programmaticStreamSerializationAllowed = 1;
    cfg.attrs = at;
    cfg.numAttrs = 1;
    cudaLaunchKernelEx(&cfg, kern, args...);
}

extern "C" void kernel_launch(void* const* d_in, const int* in_sizes, int n_in,
                              void* d_out, int out_size)
{
    const float* x  = (const float*)d_in[0];
    const float* Wq = (const float*)d_in[1];
    const float* bq = (const float*)d_in[2];
    const float* Wk = (const float*)d_in[3];
    const float* bk = (const float*)d_in[4];
    const float* Wv = (const float*)d_in[5];
    const float* bv = (const float*)d_in[6];
    const float* Wo = (const float*)d_in[7];
    const float* bo = (const float*)d_in[8];
    const float* hs = (const float*)d_in[9];
    float* out = (float*)d_out;

    float *p0, *p1, *p2, *p3, *o0, *o1, *o2, *o3, *ao;
    cudaGetSymbolAddress((void**)&p0, g_p0);
    cudaGetSymbolAddress((void**)&p1, g_p1);
    cudaGetSymbolAddress((void**)&p2, g_p2);
    cudaGetSymbolAddress((void**)&p3, g_p3);
    cudaGetSymbolAddress((void**)&o0, g_o0);
    cudaGetSymbolAddress((void**)&o1, g_o1);
    cudaGetSymbolAddress((void**)&o2, g_o2);
    cudaGetSymbolAddress((void**)&o3, g_o3);
    cudaGetSymbolAddress((void**)&ao, g_ao);

    cudaFuncSetAttribute(attn_fused, cudaFuncAttributeMaxDynamicSharedMemorySize, ATTN_SMEM_BYTES);

    launch_pdl(gemm_tf32<8>, dim3(16, 12, 4), dim3(256), 0,
               x, Wq, Wk, Wv, p0, p1, p2, p3, 3 * EE);
    launch_pdl(post_qkv_w, dim3(MM / 8), dim3(256), 0, x, bq, bk, bv);
    launch_pdl(attn_fused, dim3(8, 4, BB * HH), dim3(256), (size_t)ATTN_SMEM_BYTES, hs);
    launch_pdl(attn_combine, dim3((BB * HH * SS) / 8), dim3(256), 0);
    launch_pdl(gemm_tf32<8>, dim3(16, 4, 4), dim3(256), 0,
               (const float*)ao, Wo, Wo, Wo, o0, o1, o2, o3, EE);
    launch_pdl(post_out_w, dim3(MM / 8), dim3(256), 0, bo, out);
}